// round 13
// baseline (speedup 1.0000x reference)
#include <cuda_runtime.h>
#include <cuda_fp16.h>
#include <stdint.h>

#define NN 50000
#define NE 800000

// ---------------- device scratch ----------------
__device__ float g_agg[(size_t)NN * 128];
__device__ float g_cs4[(size_t)NN * 4];
__device__ float g_H1a[(size_t)NN * 128];
__device__ float g_H1b[(size_t)NN * 128];
__device__ uint32_t g_hpack[(size_t)NN * 128];   // (lo16<<16)|hi16 fp16 split of h
__device__ uint32_t g_W1ahi[128 * 64], g_W1alo[128 * 64];
__device__ uint32_t g_W1bhi[128 * 64], g_W1blo[128 * 64];
__device__ uint32_t g_W2hi[128 * 64];
__device__ uint32_t g_W3hi[128 * 64];
__device__ uint32_t g_Wn1ahi[128 * 64], g_Wn1alo[128 * 64];
__device__ uint32_t g_Wn1bhi[128 * 64], g_Wn1blo[128 * 64];
__device__ uint32_t g_Wn2hi[128 * 64],  g_Wn2lo[128 * 64];

__device__ __forceinline__ unsigned short f2h(float x) {
    __half v = __float2half(x);
    return *reinterpret_cast<unsigned short*>(&v);
}
__device__ __forceinline__ float h2f(unsigned short u) {
    __half v = *reinterpret_cast<__half*>(&u);
    return __half2float(v);
}
__device__ __forceinline__ float silu_f(float x) { return x / (1.0f + __expf(-x)); }
__device__ __forceinline__ void red4(float* p, float a, float b, float c, float d) {
    asm volatile("red.global.add.v4.f32 [%0], {%1,%2,%3,%4};"
                 :: "l"(p), "f"(a), "f"(b), "f"(c), "f"(d) : "memory");
}
__device__ __forceinline__ uint32_t smem_u32(const void* p) {
    uint32_t a;
    asm("{ .reg .u64 t; cvta.to.shared.u64 t, %1; cvt.u32.u64 %0, t; }" : "=r"(a) : "l"(p));
    return a;
}
__device__ __forceinline__ void cp16(uint32_t dst, const void* src) {
    asm volatile("cp.async.ca.shared.global [%0], [%1], 16;" :: "r"(dst), "l"(src));
}
__device__ __forceinline__ void cp_commit() {
    asm volatile("cp.async.commit_group;" ::: "memory");
}
__device__ __forceinline__ void wg0() { asm volatile("cp.async.wait_group 0;" ::: "memory"); }
__device__ __forceinline__ void wg1() { asm volatile("cp.async.wait_group 1;" ::: "memory"); }
__device__ __forceinline__ void ldsm4(uint32_t* r, uint32_t addr) {
    asm volatile("ldmatrix.sync.aligned.m8n8.x4.shared.b16 {%0,%1,%2,%3}, [%4];"
        : "=r"(r[0]), "=r"(r[1]), "=r"(r[2]), "=r"(r[3]) : "r"(addr));
}
#define MMAH(ac, a, b0, b1) \
    asm volatile("mma.sync.aligned.m16n8k16.row.col.f32.f16.f16.f32 " \
        "{%0,%1,%2,%3}, {%4,%5,%6,%7}, {%8,%9}, {%0,%1,%2,%3};" \
        : "+f"((ac)[0]), "+f"((ac)[1]), "+f"((ac)[2]), "+f"((ac)[3]) \
        : "r"((a)[0]), "r"((a)[1]), "r"((a)[2]), "r"((a)[3]), "r"(b0), "r"(b1))

#define SA2 136
#define B_CH_ST  10240u
// ---- edge smem layout ----
#define MH        0u
#define E_OFFB    34816u
#define OFF_W1C   55296u
#define OFF_BIAS  64000u
#define OFF_ROW   66048u
#define OFF_COL   66560u
#define OFF_D     67072u
#define OFF_RAD   68608u
#define OFF_WSUM  69120u
#define OFF_BC2   69632u
#define OFF_SPRE  69664u      // [64][132] f32 staging = 33792
#define EDGE_SMEM 103456u
// ---- hi/lo GEMM smem layout (h1 + node kernels) ----
#define HL_AH     0u
#define HL_AL     34816u
#define HL_OFFB   69632u
#define HL_BUF_ST 20480u
#define HL_BIAS   110592u
#define HL_SMEM   111616u

extern __shared__ char dynsmem[];

// ---------------- prep ----------------
__global__ void prep_h_kernel(const float* __restrict__ h) {
    size_t i = (size_t)blockIdx.x * 256 + threadIdx.x;
    if (i < (size_t)NN * 128) {
        float v = h[i];
        unsigned short hi = f2h(v);
        unsigned short lo = f2h(v - h2f(hi));
        g_hpack[i] = (uint32_t)hi | ((uint32_t)lo << 16);
    }
}
__global__ void prep_w_kernel(const float* __restrict__ We1,
                              const float* __restrict__ We2,
                              const float* __restrict__ Wc1,
                              const float* __restrict__ Wn1,
                              const float* __restrict__ Wn2) {
    int t = blockIdx.x * 256 + threadIdx.x;
    if (t >= 57344) return;
    int img = t >> 13, u = t & 8191, n = u >> 6, kp = u & 63;
    int k0 = kp * 2, k1 = k0 + 1;
    float v0, v1;
    if (img == 0)      { v0 = We1[k0 * 128 + n];         v1 = We1[k1 * 128 + n]; }
    else if (img == 1) { v0 = We1[(128 + k0) * 128 + n]; v1 = We1[(128 + k1) * 128 + n]; }
    else if (img == 2) { v0 = We2[k0 * 128 + n];         v1 = We2[k1 * 128 + n]; }
    else if (img == 3) { v0 = Wc1[k0 * 128 + n];         v1 = Wc1[k1 * 128 + n]; }
    else if (img == 4) { v0 = Wn1[k0 * 128 + n];         v1 = Wn1[k1 * 128 + n]; }
    else if (img == 5) { v0 = Wn1[(128 + k0) * 128 + n]; v1 = Wn1[(128 + k1) * 128 + n]; }
    else               { v0 = Wn2[k0 * 128 + n];         v1 = Wn2[k1 * 128 + n]; }
    unsigned short h0 = f2h(v0), h1 = f2h(v1);
    uint32_t hpack = (uint32_t)h0 | ((uint32_t)h1 << 16);
    uint32_t lpack = (uint32_t)f2h(v0 - h2f(h0)) | ((uint32_t)f2h(v1 - h2f(h1)) << 16);
    int o = n * 64 + kp;
    if (img == 0)      { g_W1ahi[o] = hpack; g_W1alo[o] = lpack; }
    else if (img == 1) { g_W1bhi[o] = hpack; g_W1blo[o] = lpack; }
    else if (img == 2) { g_W2hi[o] = hpack; }
    else if (img == 3) { g_W3hi[o] = hpack; }
    else if (img == 4) { g_Wn1ahi[o] = hpack; g_Wn1alo[o] = lpack; }
    else if (img == 5) { g_Wn1bhi[o] = hpack; g_Wn1blo[o] = lpack; }
    else               { g_Wn2hi[o] = hpack; g_Wn2lo[o] = lpack; }
}

// ======== hi+lo GEMM machinery (h1 + node kernels) ========
__device__ __forceinline__ void issue_chunk_hl(uint32_t sb, int buf,
                                               const uint32_t* gHi, const uint32_t* gLo, int kb) {
    int tid = threadIdx.x;
    #pragma unroll
    for (int j = 0; j < 4; j++) {
        int g = tid + 256 * j;
        int arr = g >> 9;
        int n = (g >> 2) & 127;
        int q = g & 3;
        const uint32_t* src = (arr ? gLo : gHi) + n * 64 + (kb >> 1) + q * 4;
        uint32_t dst = sb + HL_OFFB + (uint32_t)buf * HL_BUF_ST + (uint32_t)arr * B_CH_ST
                     + (uint32_t)(n * 20 + q * 4) * 4u;
        cp16(dst, src);
    }
    cp_commit();
}

__device__ __forceinline__ void mma_step_hl(uint32_t aBaseH, uint32_t aBaseL,
                                            int kb, uint32_t bBase, int kloc,
                                            int warpM, int warpN, int lane,
                                            float acc[2][8][4]) {
    uint32_t ah[2][4], al[2][4];
    const uint32_t arow = (uint32_t)(warpM * 32 + (lane & 15));
    const uint32_t aoff = (uint32_t)(kb + ((lane >> 4) << 3)) * 2u;
    #pragma unroll
    for (int mt = 0; mt < 2; mt++) {
        uint32_t ad = (arow + (uint32_t)(mt * 16)) * (SA2 * 2u) + aoff;
        ldsm4(ah[mt], aBaseH + ad);
        ldsm4(al[mt], aBaseL + ad);
    }
    const uint32_t nrow = (uint32_t)(warpN * 64 + (lane & 7) + ((lane >> 4) << 3));
    const uint32_t boffk = (uint32_t)((kloc >> 1) + ((lane >> 3) & 1) * 4) * 4u;
    #pragma unroll
    for (int p = 0; p < 4; p++) {
        uint32_t bh[4], bl[4];
        uint32_t bd = (nrow + (uint32_t)(p * 16)) * 80u + boffk;
        ldsm4(bh, bBase + bd);
        ldsm4(bl, bBase + B_CH_ST + bd);
        int nt0 = p * 2, nt1 = p * 2 + 1;
        #pragma unroll
        for (int mt = 0; mt < 2; mt++) {
            MMAH(acc[mt][nt0], ah[mt], bh[0], bh[1]);
            MMAH(acc[mt][nt0], ah[mt], bl[0], bl[1]);
            MMAH(acc[mt][nt0], al[mt], bh[0], bh[1]);
            MMAH(acc[mt][nt1], ah[mt], bh[2], bh[3]);
            MMAH(acc[mt][nt1], ah[mt], bl[2], bl[3]);
            MMAH(acc[mt][nt1], al[mt], bh[2], bh[3]);
        }
    }
}

__device__ __forceinline__ void gemm_loop_hl(uint32_t sb,
    const uint32_t* gHi, const uint32_t* gLo,
    const uint32_t* nHi, const uint32_t* nLo, bool last,
    int warpM, int warpN, int lane, float acc[2][8][4]) {
    const uint32_t aH = sb + HL_AH, aL = sb + HL_AL;
    for (int c = 0; c < 4; c++) {
        if (c == 3 && last) wg0(); else wg1();
        __syncthreads();
        uint32_t bB = sb + HL_OFFB + (uint32_t)(c & 1) * HL_BUF_ST;
        mma_step_hl(aH, aL, c * 32,      bB, 0,  warpM, warpN, lane, acc);
        mma_step_hl(aH, aL, c * 32 + 16, bB, 16, warpM, warpN, lane, acc);
        __syncthreads();
        if (c < 2)      issue_chunk_hl(sb, c & 1, gHi, gLo, (c + 2) * 32);
        else if (!last) issue_chunk_hl(sb, c & 1, nHi, nLo, (c - 2) * 32);
    }
}

__device__ __forceinline__ void build_A_from_hpack(char* smem, const uint32_t* src_rows,
                                                   int tid) {
    uint16_t* aH = (uint16_t*)(smem + HL_AH);
    uint16_t* aL = (uint16_t*)(smem + HL_AL);
    int e = tid >> 1, half = tid & 1;
    const uint4* p = (const uint4*)(src_rows) + half * 16;
    #pragma unroll 4
    for (int j0 = 0; j0 < 64; j0 += 8) {
        uint4 v0 = p[j0 >> 2], v1 = p[(j0 >> 2) + 1];
        uint4 h4, l4;
        h4.x = (v0.x & 0xFFFFu) | (v0.y << 16);  l4.x = (v0.x >> 16) | (v0.y & 0xFFFF0000u);
        h4.y = (v0.z & 0xFFFFu) | (v0.w << 16);  l4.y = (v0.z >> 16) | (v0.w & 0xFFFF0000u);
        h4.z = (v1.x & 0xFFFFu) | (v1.y << 16);  l4.z = (v1.x >> 16) | (v1.y & 0xFFFF0000u);
        h4.w = (v1.z & 0xFFFFu) | (v1.w << 16);  l4.w = (v1.z >> 16) | (v1.w & 0xFFFF0000u);
        int o = e * SA2 + half * 64 + j0;
        *(uint4*)(aH + o) = h4;
        *(uint4*)(aL + o) = l4;
    }
}

// ======== hi-only machinery (edge kernel) ========
__device__ __forceinline__ void issue_chunk_e(uint32_t sb, int buf,
                                              const uint32_t* gHi, int kb) {
    int tid = threadIdx.x;
    #pragma unroll
    for (int j = 0; j < 2; j++) {
        int g = tid + 256 * j;
        int n = (g >> 2) & 127;
        int q = g & 3;
        const uint32_t* src = gHi + n * 64 + (kb >> 1) + q * 4;
        uint32_t dst = sb + E_OFFB + (uint32_t)buf * B_CH_ST
                     + (uint32_t)(n * 20 + q * 4) * 4u;
        cp16(dst, src);
    }
    cp_commit();
}

__device__ __forceinline__ void mma_step_e(uint32_t aBase, int kb,
                                           uint32_t bBase, int kloc,
                                           int warpM, int warpN, int lane,
                                           float acc[2][8][4]) {
    uint32_t ah[2][4];
    const uint32_t arow = (uint32_t)(warpM * 32 + (lane & 15));
    const uint32_t aoff = (uint32_t)(kb + ((lane >> 4) << 3)) * 2u;
    #pragma unroll
    for (int mt = 0; mt < 2; mt++) {
        uint32_t ad = (arow + (uint32_t)(mt * 16)) * (SA2 * 2u) + aoff;
        ldsm4(ah[mt], aBase + ad);
    }
    const uint32_t nrow = (uint32_t)(warpN * 64 + (lane & 7) + ((lane >> 4) << 3));
    const uint32_t boffk = (uint32_t)((kloc >> 1) + ((lane >> 3) & 1) * 4) * 4u;
    #pragma unroll
    for (int p = 0; p < 4; p++) {
        uint32_t bh[4];
        uint32_t bd = (nrow + (uint32_t)(p * 16)) * 80u + boffk;
        ldsm4(bh, bBase + bd);
        int nt0 = p * 2, nt1 = p * 2 + 1;
        #pragma unroll
        for (int mt = 0; mt < 2; mt++) {
            MMAH(acc[mt][nt0], ah[mt], bh[0], bh[1]);
            MMAH(acc[mt][nt1], ah[mt], bh[2], bh[3]);
        }
    }
}

__device__ __forceinline__ void gemm_loop_e(uint32_t sb,
    const uint32_t* gHi, const uint32_t* nHi,
    int warpM, int warpN, int lane, float acc[2][8][4]) {
    const uint32_t aB = sb + MH;
    for (int c = 0; c < 4; c++) {
        wg1();
        __syncthreads();
        uint32_t bB = sb + E_OFFB + (uint32_t)(c & 1) * B_CH_ST;
        mma_step_e(aB, c * 32,      bB, 0,  warpM, warpN, lane, acc);
        mma_step_e(aB, c * 32 + 16, bB, 16, warpM, warpN, lane, acc);
        __syncthreads();
        if (c < 2) issue_chunk_e(sb, c & 1, gHi, (c + 2) * 32);
        else       issue_chunk_e(sb, c & 1, nHi, (c - 2) * 32);
    }
}

__device__ __forceinline__ void gemm_loop_e_scatter(uint32_t sb,
    const uint32_t* gHi,
    int warpM, int warpN, int lane,
    const uint16_t* mh, const int* s_row, int eb,
    float* m_out, float* agg, float acc[2][8][4]) {
    const uint32_t aB = sb + MH;
    const int tid = threadIdx.x;
    for (int c = 0; c < 4; c++) {
        if (c == 3) wg0(); else wg1();
        __syncthreads();
        uint32_t bB = sb + E_OFFB + (uint32_t)(c & 1) * B_CH_ST;
        mma_step_e(aB, c * 32,      bB, 0,  warpM, warpN, lane, acc);
        mma_step_e(aB, c * 32 + 16, bB, 16, warpM, warpN, lane, acc);
        __syncthreads();
        if (c < 2) issue_chunk_e(sb, c & 1, gHi, (c + 2) * 32);
        #pragma unroll
        for (int it = 0; it < 4; it++) {
            int i = tid + it * 256;
            int e = c * 32 + (i >> 5);
            int q = (i & 31) * 4;
            uint2 hh = *(const uint2*)(mh + e * SA2 + q);
            float v0 = h2f((unsigned short)(hh.x & 0xFFFFu));
            float v1 = h2f((unsigned short)(hh.x >> 16));
            float v2 = h2f((unsigned short)(hh.y & 0xFFFFu));
            float v3 = h2f((unsigned short)(hh.y >> 16));
            *(float4*)(m_out + (size_t)(eb + e) * 128 + q) = make_float4(v0, v1, v2, v3);
            red4(agg + (size_t)s_row[e] * 128 + q, v0, v1, v2, v3);
        }
    }
}

// ---------------- H1 precompute kernel ----------------
__global__ void __launch_bounds__(256, 2) h1_kernel() {
    char* smem = dynsmem;
    const uint32_t sb = smem_u32(smem);
    const int tid = threadIdx.x;
    const int lane = tid & 31, wid = tid >> 5;
    const int warpM = wid & 3, warpN = wid >> 2;
    const int gr = lane >> 2, ci = lane & 3;
    const int nb = blockIdx.x * 128;

    {
        int e = tid >> 1;
        int node = nb + e; if (node >= NN) node = NN - 1;
        build_A_from_hpack(smem, g_hpack + (size_t)node * 128, tid);
    }
    issue_chunk_hl(sb, 0, g_W1ahi, g_W1alo, 0);
    issue_chunk_hl(sb, 1, g_W1ahi, g_W1alo, 32);

    float acc[2][8][4];
    #pragma unroll
    for (int a = 0; a < 2; a++)
        #pragma unroll
        for (int b = 0; b < 8; b++)
            #pragma unroll
            for (int d = 0; d < 4; d++) acc[a][b][d] = 0.0f;

    gemm_loop_hl(sb, g_W1ahi, g_W1alo, g_W1bhi, g_W1blo, false, warpM, warpN, lane, acc);
    #pragma unroll
    for (int mt = 0; mt < 2; mt++) {
        int row = nb + warpM * 32 + mt * 16 + gr;
        #pragma unroll
        for (int nt = 0; nt < 8; nt++) {
            int c = warpN * 64 + nt * 8 + ci * 2;
            if (row < NN)
                *(float2*)(g_H1a + (size_t)row * 128 + c) = make_float2(acc[mt][nt][0], acc[mt][nt][1]);
            if (row + 8 < NN)
                *(float2*)(g_H1a + (size_t)(row + 8) * 128 + c) = make_float2(acc[mt][nt][2], acc[mt][nt][3]);
            acc[mt][nt][0] = acc[mt][nt][1] = acc[mt][nt][2] = acc[mt][nt][3] = 0.0f;
        }
    }
    gemm_loop_hl(sb, g_W1bhi, g_W1blo, nullptr, nullptr, true, warpM, warpN, lane, acc);
    #pragma unroll
    for (int mt = 0; mt < 2; mt++) {
        int row = nb + warpM * 32 + mt * 16 + gr;
        #pragma unroll
        for (int nt = 0; nt < 8; nt++) {
            int c = warpN * 64 + nt * 8 + ci * 2;
            if (row < NN)
                *(float2*)(g_H1b + (size_t)row * 128 + c) = make_float2(acc[mt][nt][0], acc[mt][nt][1]);
            if (row + 8 < NN)
                *(float2*)(g_H1b + (size_t)(row + 8) * 128 + c) = make_float2(acc[mt][nt][2], acc[mt][nt][3]);
        }
    }
}

// ---------------- node MMA kernel ----------------
__global__ void __launch_bounds__(256, 2) node_kernel(
    const float* __restrict__ coord,
    const float* __restrict__ bn1, const float* __restrict__ bn2,
    const float* __restrict__ agg, const float* __restrict__ cs4,
    float* __restrict__ h_out, float* __restrict__ c_out)
{
    char* smem = dynsmem;
    const uint32_t sb = smem_u32(smem);
    const int tid = threadIdx.x;
    const int lane = tid & 31, wid = tid >> 5;
    const int warpM = wid & 3, warpN = wid >> 2;
    const int gr = lane >> 2, ci = lane & 3;
    const int nb = blockIdx.x * 128;

    uint16_t* aH = (uint16_t*)(smem + HL_AH);
    uint16_t* aL = (uint16_t*)(smem + HL_AL);
    float* sbias = (float*)(smem + HL_BIAS);

    if (tid < 128) { sbias[tid] = bn1[tid]; sbias[128 + tid] = bn2[tid]; }

    {
        int e = tid >> 1;
        int node = nb + e; if (node >= NN) node = NN - 1;
        build_A_from_hpack(smem, g_hpack + (size_t)node * 128, tid);
    }
    issue_chunk_hl(sb, 0, g_Wn1ahi, g_Wn1alo, 0);
    issue_chunk_hl(sb, 1, g_Wn1ahi, g_Wn1alo, 32);

    float acc[2][8][4];
    #pragma unroll
    for (int a = 0; a < 2; a++)
        #pragma unroll
        for (int b = 0; b < 8; b++)
            #pragma unroll
            for (int d = 0; d < 4; d++) acc[a][b][d] = 0.0f;

    gemm_loop_hl(sb, g_Wn1ahi, g_Wn1alo, g_Wn1bhi, g_Wn1blo, false, warpM, warpN, lane, acc);

    {
        int e = tid >> 1, half = tid & 1;
        int node = nb + e; if (node >= NN) node = NN - 1;
        const float4* p = (const float4*)(agg + (size_t)node * 128 + half * 64);
        #pragma unroll 4
        for (int j0 = 0; j0 < 64; j0 += 4) {
            float4 v = p[j0 >> 2];
            unsigned short h0 = f2h(v.x), h1 = f2h(v.y), h2 = f2h(v.z), h3 = f2h(v.w);
            uint2 hp2, lp2;
            hp2.x = (uint32_t)h0 | ((uint32_t)h1 << 16);
            hp2.y = (uint32_t)h2 | ((uint32_t)h3 << 16);
            lp2.x = (uint32_t)f2h(v.x - h2f(h0)) | ((uint32_t)f2h(v.y - h2f(h1)) << 16);
            lp2.y = (uint32_t)f2h(v.z - h2f(h2)) | ((uint32_t)f2h(v.w - h2f(h3)) << 16);
            int o = e * SA2 + half * 64 + j0;
            *(uint2*)(aH + o) = hp2;
            *(uint2*)(aL + o) = lp2;
        }
    }
    __syncthreads();

    gemm_loop_hl(sb, g_Wn1bhi, g_Wn1blo, g_Wn2hi, g_Wn2lo, false, warpM, warpN, lane, acc);

    #pragma unroll
    for (int mt = 0; mt < 2; mt++) {
        int r0 = warpM * 32 + mt * 16 + gr, r1 = r0 + 8;
        #pragma unroll
        for (int nt = 0; nt < 8; nt++) {
            int c = warpN * 64 + nt * 8 + ci * 2;
            float b0 = sbias[c], b1 = sbias[c + 1];
            float x0 = silu_f(acc[mt][nt][0] + b0), x1 = silu_f(acc[mt][nt][1] + b1);
            float x2 = silu_f(acc[mt][nt][2] + b0), x3 = silu_f(acc[mt][nt][3] + b1);
            unsigned short h0 = f2h(x0), h1 = f2h(x1), h2 = f2h(x2), h3 = f2h(x3);
            *(uint32_t*)(aH + r0 * SA2 + c) = (uint32_t)h0 | ((uint32_t)h1 << 16);
            *(uint32_t*)(aL + r0 * SA2 + c) =
                (uint32_t)f2h(x0 - h2f(h0)) | ((uint32_t)f2h(x1 - h2f(h1)) << 16);
            *(uint32_t*)(aH + r1 * SA2 + c) = (uint32_t)h2 | ((uint32_t)h3 << 16);
            *(uint32_t*)(aL + r1 * SA2 + c) =
                (uint32_t)f2h(x2 - h2f(h2)) | ((uint32_t)f2h(x3 - h2f(h3)) << 16);
            acc[mt][nt][0] = acc[mt][nt][1] = acc[mt][nt][2] = acc[mt][nt][3] = 0.0f;
        }
    }
    __syncthreads();

    gemm_loop_hl(sb, g_Wn2hi, g_Wn2lo, nullptr, nullptr, true, warpM, warpN, lane, acc);

    #pragma unroll
    for (int mt = 0; mt < 2; mt++) {
        int row = nb + warpM * 32 + mt * 16 + gr;
        #pragma unroll
        for (int nt = 0; nt < 8; nt++) {
            int c = warpN * 64 + nt * 8 + ci * 2;
            float b0 = sbias[128 + c], b1 = sbias[128 + c + 1];
            if (row < NN)
                *(float2*)(h_out + (size_t)row * 128 + c) =
                    make_float2(acc[mt][nt][0] + b0, acc[mt][nt][1] + b1);
            if (row + 8 < NN)
                *(float2*)(h_out + (size_t)(row + 8) * 128 + c) =
                    make_float2(acc[mt][nt][2] + b0, acc[mt][nt][3] + b1);
        }
    }

    if (tid < 128) {
        int node = nb + tid;
        if (node < NN) {
            float4 s = *(const float4*)(cs4 + (size_t)node * 4);
            float dn = fmaxf(s.w, 1.0f);
            c_out[node * 3 + 0] = coord[node * 3 + 0] + s.x / dn;
            c_out[node * 3 + 1] = coord[node * 3 + 1] + s.y / dn;
            c_out[node * 3 + 2] = coord[node * 3 + 2] + s.z / dn;
        }
    }
}

// ---------------- edge kernel ----------------
__global__ void __launch_bounds__(256, 2) edge_kernel(
    const float* __restrict__ coord, const float* __restrict__ eattr,
    const int* __restrict__ ei, const float* __restrict__ We1,
    const float* __restrict__ be1, const float* __restrict__ be2,
    const float* __restrict__ bc1, const float* __restrict__ Wc2,
    const float* __restrict__ bc2,
    float* __restrict__ m_out, float* __restrict__ agg, float* __restrict__ cs4)
{
    char* smem = dynsmem;
    const uint32_t sb = smem_u32(smem);
    const int tid = threadIdx.x;
    const int lane = tid & 31, wid = tid >> 5;
    const int warpM = wid & 3, warpN = wid >> 2;
    const int gr = lane >> 2, ci = lane & 3;
    const int eb = blockIdx.x * 128;

    uint16_t* mh  = (uint16_t*)(smem + MH);
    float* w1c    = (float*)(smem + OFF_W1C);
    float* sbias  = (float*)(smem + OFF_BIAS);
    int* s_row    = (int*)(smem + OFF_ROW);
    int* s_col    = (int*)(smem + OFF_COL);
    float* s_dx   = (float*)(smem + OFF_D);
    float* s_dy   = s_dx + 128;
    float* s_dz   = s_dx + 256;
    float* s_rad  = (float*)(smem + OFF_RAD);
    float* s_wsum = (float*)(smem + OFF_WSUM);
    float* spre   = (float*)(smem + OFF_SPRE);

    for (int i = tid; i < 17 * 128; i += 256) w1c[i] = We1[256 * 128 + i];
    if (tid < 128) {
        sbias[tid] = be1[tid]; sbias[128 + tid] = be2[tid];
        sbias[256 + tid] = bc1[tid]; sbias[384 + tid] = Wc2[tid];
        s_wsum[tid] = 0.0f;
    }
    if (tid == 0) *(float*)(smem + OFF_BC2) = bc2[0];
    if (tid < 128) {
        int g = eb + tid;
        int r = ei[g], c = ei[NE + g];
        s_row[tid] = r; s_col[tid] = c;
        float dx = coord[r * 3 + 0] - coord[c * 3 + 0];
        float dy = coord[r * 3 + 1] - coord[c * 3 + 1];
        float dz = coord[r * 3 + 2] - coord[c * 3 + 2];
        s_dx[tid] = dx; s_dy[tid] = dy; s_dz[tid] = dz;
        s_rad[tid] = dx * dx + dy * dy + dz * dz;
    }
    issue_chunk_e(sb, 0, g_W2hi, 0);
    issue_chunk_e(sb, 1, g_W2hi, 32);
    __syncthreads();

    // pre phase, 2 halves of 64 edges:
    //  (a) warp-cooperative coalesced gather of H1a[row]+H1b[col] -> spre (fp32)
    //  (b) m1 = silu(spre + be1 + [rad|eattr]@We1c) -> fp16 mh
    #pragma unroll
    for (int hb = 0; hb < 2; hb++) {
        {
            int w = tid >> 5, q = (tid & 31) * 4;
            #pragma unroll
            for (int i = 0; i < 8; i++) {
                int le = w * 8 + i;
                int eg = hb * 64 + le;
                float4 va = *(const float4*)(g_H1a + (size_t)s_row[eg] * 128 + q);
                float4 vb = *(const float4*)(g_H1b + (size_t)s_col[eg] * 128 + q);
                *(float4*)(spre + le * 132 + q) =
                    make_float4(va.x + vb.x, va.y + vb.y, va.z + vb.z, va.w + vb.w);
            }
        }
        __syncthreads();
        {
            int le = tid >> 2, t4 = tid & 3;
            int eg = hb * 64 + le;
            float x[17];
            x[0] = s_rad[eg];
            const float* ea = eattr + (size_t)(eb + eg) * 16;
            #pragma unroll
            for (int j = 0; j < 16; j++) x[j + 1] = ea[j];
            const float4* w4 = (const float4*)w1c;
            #pragma unroll
            for (int cb = 0; cb < 2; cb++) {
                int cc0 = t4 * 32 + cb * 16;
                int q0 = cc0 >> 2;
                float pre[16];
                #pragma unroll
                for (int i = 0; i < 4; i++) {
                    float4 v = *(const float4*)(spre + le * 132 + cc0 + i * 4);
                    pre[i * 4 + 0] = v.x + sbias[cc0 + i * 4 + 0];
                    pre[i * 4 + 1] = v.y + sbias[cc0 + i * 4 + 1];
                    pre[i * 4 + 2] = v.z + sbias[cc0 + i * 4 + 2];
                    pre[i * 4 + 3] = v.w + sbias[cc0 + i * 4 + 3];
                }
                #pragma unroll
                for (int j = 0; j < 17; j++) {
                    float xj = x[j];
                    #pragma unroll
                    for (int i = 0; i < 4; i++) {
                        float4 wv = w4[j * 32 + q0 + i];
                        pre[i * 4 + 0] = fmaf(xj, wv.x, pre[i * 4 + 0]);
                        pre[i * 4 + 1] = fmaf(xj, wv.y, pre[i * 4 + 1]);
                        pre[i * 4 + 2] = fmaf(xj, wv.z, pre[i * 4 + 2]);
                        pre[i * 4 + 3] = fmaf(xj, wv.w, pre[i * 4 + 3]);
                    }
                }
                #pragma unroll
                for (int i = 0; i < 16; i += 2) {
                    float s0 = silu_f(pre[i]), s1 = silu_f(pre[i + 1]);
                    *(uint32_t*)(mh + eg * SA2 + cc0 + i) =
                        (uint32_t)f2h(s0) | ((uint32_t)f2h(s1) << 16);
                }
            }
        }
        __syncthreads();
    }

    float acc[2][8][4];
    #pragma unroll
    for (int a = 0; a < 2; a++)
        #pragma unroll
        for (int b = 0; b < 8; b++)
            #pragma unroll
            for (int d = 0; d < 4; d++) acc[a][b][d] = 0.0f;

    gemm_loop_e(sb, g_W2hi, g_W3hi, warpM, warpN, lane, acc);

    #pragma unroll
    for (int mt = 0; mt < 2; mt++) {
        int e0 = warpM * 32 + mt * 16 + gr, e1 = e0 + 8;
        #pragma unroll
        for (int nt = 0; nt < 8; nt++) {
            int c = warpN * 64 + nt * 8 + ci * 2;
            float b0 = sbias[128 + c], b1 = sbias[128 + c + 1];
            float x0 = silu_f(acc[mt][nt][0] + b0), x1 = silu_f(acc[mt][nt][1] + b1);
            float x2 = silu_f(acc[mt][nt][2] + b0), x3 = silu_f(acc[mt][nt][3] + b1);
            *(uint32_t*)(mh + e0 * SA2 + c) = (uint32_t)f2h(x0) | ((uint32_t)f2h(x1) << 16);
            *(uint32_t*)(mh + e1 * SA2 + c) = (uint32_t)f2h(x2) | ((uint32_t)f2h(x3) << 16);
            acc[mt][nt][0] = acc[mt][nt][1] = acc[mt][nt][2] = acc[mt][nt][3] = 0.0f;
        }
    }
    __syncthreads();

    gemm_loop_e_scatter(sb, g_W3hi, warpM, warpN, lane,
                        mh, s_row, eb, m_out, agg, acc);

    {
        float part[2][2] = {{0.f, 0.f}, {0.f, 0.f}};
        #pragma unroll
        for (int mt = 0; mt < 2; mt++)
            #pragma unroll
            for (int nt = 0; nt < 8; nt++) {
                int c = warpN * 64 + nt * 8 + ci * 2;
                float b0 = sbias[256 + c], b1 = sbias[256 + c + 1];
                float w0 = sbias[384 + c], w1 = sbias[384 + c + 1];
                part[mt][0] += silu_f(acc[mt][nt][0] + b0) * w0 + silu_f(acc[mt][nt][1] + b1) * w1;
                part[mt][1] += silu_f(acc[mt][nt][2] + b0) * w0 + silu_f(acc[mt][nt][3] + b1) * w1;
            }
        #pragma unroll
        for (int off = 1; off <= 2; off <<= 1) {
            #pragma unroll
            for (int mt = 0; mt < 2; mt++) {
                part[mt][0] += __shfl_xor_sync(0xFFFFFFFFu, part[mt][0], off);
                part[mt][1] += __shfl_xor_sync(0xFFFFFFFFu, part[mt][1], off);
            }
        }
        if (ci == 0) {
            #pragma unroll
            for (int mt = 0; mt < 2; mt++) {
                int r0 = warpM * 32 + mt * 16 + gr;
                atomicAdd(&s_wsum[r0], part[mt][0]);
                atomicAdd(&s_wsum[r0 + 8], part[mt][1]);
            }
        }
    }
    __syncthreads();

    if (tid < 128) {
        float w = s_wsum[tid] + *(float*)(smem + OFF_BC2);
        int r = s_row[tid];
        red4(cs4 + (size_t)r * 4, s_dx[tid] * w, s_dy[tid] * w, s_dz[tid] * w, 1.0f);
    }
}

extern "C" void kernel_launch(void* const* d_in, const int* in_sizes, int n_in,
                              void* d_out, int out_size)
{
    const float* h     = (const float*)d_in[0];
    const float* coord = (const float*)d_in[1];
    const float* eattr = (const float*)d_in[2];
    const int*   ei    = (const int*)d_in[3];
    const float* We1 = (const float*)d_in[4];
    const float* be1 = (const float*)d_in[5];
    const float* We2 = (const float*)d_in[6];
    const float* be2 = (const float*)d_in[7];
    const float* Wn1 = (const float*)d_in[8];
    const float* bn1 = (const float*)d_in[9];
    const float* Wn2 = (const float*)d_in[10];
    const float* bn2 = (const float*)d_in[11];
    const float* Wc1 = (const float*)d_in[12];
    const float* bc1 = (const float*)d_in[13];
    const float* Wc2 = (const float*)d_in[14];
    const float* bc2 = (const float*)d_in[15];

    float* out   = (float*)d_out;
    float* h_out = out;
    float* c_out = out + (size_t)NN * 128;
    float* m_out = c_out + (size_t)NN * 3;

    void *p_agg, *p_cs4;
    cudaGetSymbolAddress(&p_agg, g_agg);
    cudaGetSymbolAddress(&p_cs4, g_cs4);
    cudaMemsetAsync(p_agg, 0, (size_t)NN * 128 * sizeof(float), 0);
    cudaMemsetAsync(p_cs4, 0, (size_t)NN * 4 * sizeof(float), 0);

    prep_h_kernel<<<(NN * 128 + 255) / 256, 256>>>(h);
    prep_w_kernel<<<224, 256>>>(We1, We2, Wc1, Wn1, Wn2);

    cudaFuncSetAttribute(h1_kernel, cudaFuncAttributeMaxDynamicSharedMemorySize, HL_SMEM);
    cudaFuncSetAttribute(node_kernel, cudaFuncAttributeMaxDynamicSharedMemorySize, HL_SMEM);
    cudaFuncSetAttribute(edge_kernel, cudaFuncAttributeMaxDynamicSharedMemorySize, EDGE_SMEM);

    h1_kernel<<<(NN + 127) / 128, 256, HL_SMEM>>>();

    edge_kernel<<<NE / 128, 256, EDGE_SMEM>>>(
        coord, eattr, ei, We1, be1, be2, bc1, Wc2, bc2,
        m_out, (float*)p_agg, (float*)p_cs4);

    node_kernel<<<(NN + 127) / 128, 256, HL_SMEM>>>(
        coord, bn1, bn2, (const float*)p_agg, (const float*)p_cs4, h_out, c_out);
}

// round 16
// speedup vs baseline: 1.6690x; 1.6690x over previous
#include <cuda_runtime.h>
#include <cuda_fp16.h>
#include <stdint.h>

#define NN 50000
#define NE 800000

// ---------------- device scratch ----------------
__device__ float g_agg[(size_t)NN * 128];
__device__ float g_cs4[(size_t)NN * 4];
__device__ float g_H1a[(size_t)NN * 128];
__device__ float g_H1b[(size_t)NN * 128];
__device__ uint32_t g_hpack[(size_t)NN * 128];   // (lo16<<16)|hi16 fp16 split of h
__device__ uint32_t g_W1ahi[128 * 64], g_W1alo[128 * 64];
__device__ uint32_t g_W1bhi[128 * 64], g_W1blo[128 * 64];
__device__ uint32_t g_W2hi[128 * 64];
__device__ uint32_t g_W3hi[128 * 64];
__device__ uint32_t g_Wn1ahi[128 * 64], g_Wn1alo[128 * 64];
__device__ uint32_t g_Wn1bhi[128 * 64], g_Wn1blo[128 * 64];
__device__ uint32_t g_Wn2hi[128 * 64],  g_Wn2lo[128 * 64];

__device__ __forceinline__ unsigned short f2h(float x) {
    __half v = __float2half(x);
    return *reinterpret_cast<unsigned short*>(&v);
}
__device__ __forceinline__ float h2f(unsigned short u) {
    __half v = *reinterpret_cast<__half*>(&u);
    return __half2float(v);
}
__device__ __forceinline__ float silu_f(float x) { return x / (1.0f + __expf(-x)); }
__device__ __forceinline__ void red4(float* p, float a, float b, float c, float d) {
    asm volatile("red.global.add.v4.f32 [%0], {%1,%2,%3,%4};"
                 :: "l"(p), "f"(a), "f"(b), "f"(c), "f"(d) : "memory");
}
__device__ __forceinline__ uint32_t smem_u32(const void* p) {
    uint32_t a;
    asm("{ .reg .u64 t; cvta.to.shared.u64 t, %1; cvt.u32.u64 %0, t; }" : "=r"(a) : "l"(p));
    return a;
}
__device__ __forceinline__ void cp16(uint32_t dst, const void* src) {
    asm volatile("cp.async.ca.shared.global [%0], [%1], 16;" :: "r"(dst), "l"(src));
}
__device__ __forceinline__ void cp_commit() {
    asm volatile("cp.async.commit_group;" ::: "memory");
}
__device__ __forceinline__ void wg0() { asm volatile("cp.async.wait_group 0;" ::: "memory"); }
__device__ __forceinline__ void wg1() { asm volatile("cp.async.wait_group 1;" ::: "memory"); }
__device__ __forceinline__ void ldsm4(uint32_t* r, uint32_t addr) {
    asm volatile("ldmatrix.sync.aligned.m8n8.x4.shared.b16 {%0,%1,%2,%3}, [%4];"
        : "=r"(r[0]), "=r"(r[1]), "=r"(r[2]), "=r"(r[3]) : "r"(addr));
}
#define MMAH(ac, a, b0, b1) \
    asm volatile("mma.sync.aligned.m16n8k16.row.col.f32.f16.f16.f32 " \
        "{%0,%1,%2,%3}, {%4,%5,%6,%7}, {%8,%9}, {%0,%1,%2,%3};" \
        : "+f"((ac)[0]), "+f"((ac)[1]), "+f"((ac)[2]), "+f"((ac)[3]) \
        : "r"((a)[0]), "r"((a)[1]), "r"((a)[2]), "r"((a)[3]), "r"(b0), "r"(b1))

#define SA2 136
#define B_CH_ST  10240u
// ---- edge smem layout (R12 + s_eatt) ----
#define MH        0u
#define E_OFFB    34816u
#define OFF_W1C   55296u
#define OFF_BIAS  64000u
#define OFF_ROW   66048u
#define OFF_COL   66560u
#define OFF_D     67072u
#define OFF_RAD   68608u
#define OFF_WSUM  69120u
#define OFF_BC2   69632u
#define OFF_EATT  69664u      // [128][16] f32 = 8192
#define EDGE_SMEM 77856u
// ---- hi/lo GEMM smem layout (h1 + node kernels) ----
#define HL_AH     0u
#define HL_AL     34816u
#define HL_OFFB   69632u
#define HL_BUF_ST 20480u
#define HL_BIAS   110592u
#define HL_SMEM   111616u

extern __shared__ char dynsmem[];

// ---------------- prep ----------------
__global__ void prep_h_kernel(const float* __restrict__ h) {
    size_t i = (size_t)blockIdx.x * 256 + threadIdx.x;
    if (i < (size_t)NN * 128) {
        float v = h[i];
        unsigned short hi = f2h(v);
        unsigned short lo = f2h(v - h2f(hi));
        g_hpack[i] = (uint32_t)hi | ((uint32_t)lo << 16);
    }
}
__global__ void prep_w_kernel(const float* __restrict__ We1,
                              const float* __restrict__ We2,
                              const float* __restrict__ Wc1,
                              const float* __restrict__ Wn1,
                              const float* __restrict__ Wn2) {
    int t = blockIdx.x * 256 + threadIdx.x;
    if (t >= 57344) return;
    int img = t >> 13, u = t & 8191, n = u >> 6, kp = u & 63;
    int k0 = kp * 2, k1 = k0 + 1;
    float v0, v1;
    if (img == 0)      { v0 = We1[k0 * 128 + n];         v1 = We1[k1 * 128 + n]; }
    else if (img == 1) { v0 = We1[(128 + k0) * 128 + n]; v1 = We1[(128 + k1) * 128 + n]; }
    else if (img == 2) { v0 = We2[k0 * 128 + n];         v1 = We2[k1 * 128 + n]; }
    else if (img == 3) { v0 = Wc1[k0 * 128 + n];         v1 = Wc1[k1 * 128 + n]; }
    else if (img == 4) { v0 = Wn1[k0 * 128 + n];         v1 = Wn1[k1 * 128 + n]; }
    else if (img == 5) { v0 = Wn1[(128 + k0) * 128 + n]; v1 = Wn1[(128 + k1) * 128 + n]; }
    else               { v0 = Wn2[k0 * 128 + n];         v1 = Wn2[k1 * 128 + n]; }
    unsigned short h0 = f2h(v0), h1 = f2h(v1);
    uint32_t hpack = (uint32_t)h0 | ((uint32_t)h1 << 16);
    uint32_t lpack = (uint32_t)f2h(v0 - h2f(h0)) | ((uint32_t)f2h(v1 - h2f(h1)) << 16);
    int o = n * 64 + kp;
    if (img == 0)      { g_W1ahi[o] = hpack; g_W1alo[o] = lpack; }
    else if (img == 1) { g_W1bhi[o] = hpack; g_W1blo[o] = lpack; }
    else if (img == 2) { g_W2hi[o] = hpack; }
    else if (img == 3) { g_W3hi[o] = hpack; }
    else if (img == 4) { g_Wn1ahi[o] = hpack; g_Wn1alo[o] = lpack; }
    else if (img == 5) { g_Wn1bhi[o] = hpack; g_Wn1blo[o] = lpack; }
    else               { g_Wn2hi[o] = hpack; g_Wn2lo[o] = lpack; }
}

// ======== hi+lo GEMM machinery ========
__device__ __forceinline__ void issue_chunk_hl(uint32_t sb, int buf,
                                               const uint32_t* gHi, const uint32_t* gLo, int kb) {
    int tid = threadIdx.x;
    #pragma unroll
    for (int j = 0; j < 4; j++) {
        int g = tid + 256 * j;
        int arr = g >> 9;
        int n = (g >> 2) & 127;
        int q = g & 3;
        const uint32_t* src = (arr ? gLo : gHi) + n * 64 + (kb >> 1) + q * 4;
        uint32_t dst = sb + HL_OFFB + (uint32_t)buf * HL_BUF_ST + (uint32_t)arr * B_CH_ST
                     + (uint32_t)(n * 20 + q * 4) * 4u;
        cp16(dst, src);
    }
    cp_commit();
}

__device__ __forceinline__ void mma_step_hl(uint32_t aBaseH, uint32_t aBaseL,
                                            int kb, uint32_t bBase, int kloc,
                                            int warpM, int warpN, int lane,
                                            float acc[2][8][4]) {
    uint32_t ah[2][4], al[2][4];
    const uint32_t arow = (uint32_t)(warpM * 32 + (lane & 15));
    const uint32_t aoff = (uint32_t)(kb + ((lane >> 4) << 3)) * 2u;
    #pragma unroll
    for (int mt = 0; mt < 2; mt++) {
        uint32_t ad = (arow + (uint32_t)(mt * 16)) * (SA2 * 2u) + aoff;
        ldsm4(ah[mt], aBaseH + ad);
        ldsm4(al[mt], aBaseL + ad);
    }
    const uint32_t nrow = (uint32_t)(warpN * 64 + (lane & 7) + ((lane >> 4) << 3));
    const uint32_t boffk = (uint32_t)((kloc >> 1) + ((lane >> 3) & 1) * 4) * 4u;
    #pragma unroll
    for (int p = 0; p < 4; p++) {
        uint32_t bh[4], bl[4];
        uint32_t bd = (nrow + (uint32_t)(p * 16)) * 80u + boffk;
        ldsm4(bh, bBase + bd);
        ldsm4(bl, bBase + B_CH_ST + bd);
        int nt0 = p * 2, nt1 = p * 2 + 1;
        #pragma unroll
        for (int mt = 0; mt < 2; mt++) {
            MMAH(acc[mt][nt0], ah[mt], bh[0], bh[1]);
            MMAH(acc[mt][nt0], ah[mt], bl[0], bl[1]);
            MMAH(acc[mt][nt0], al[mt], bh[0], bh[1]);
            MMAH(acc[mt][nt1], ah[mt], bh[2], bh[3]);
            MMAH(acc[mt][nt1], ah[mt], bl[2], bl[3]);
            MMAH(acc[mt][nt1], al[mt], bh[2], bh[3]);
        }
    }
}

__device__ __forceinline__ void gemm_loop_hl(uint32_t sb,
    const uint32_t* gHi, const uint32_t* gLo,
    const uint32_t* nHi, const uint32_t* nLo, bool last,
    int warpM, int warpN, int lane, float acc[2][8][4]) {
    const uint32_t aH = sb + HL_AH, aL = sb + HL_AL;
    for (int c = 0; c < 4; c++) {
        if (c == 3 && last) wg0(); else wg1();
        __syncthreads();
        uint32_t bB = sb + HL_OFFB + (uint32_t)(c & 1) * HL_BUF_ST;
        mma_step_hl(aH, aL, c * 32,      bB, 0,  warpM, warpN, lane, acc);
        mma_step_hl(aH, aL, c * 32 + 16, bB, 16, warpM, warpN, lane, acc);
        __syncthreads();
        if (c < 2)      issue_chunk_hl(sb, c & 1, gHi, gLo, (c + 2) * 32);
        else if (!last) issue_chunk_hl(sb, c & 1, nHi, nLo, (c - 2) * 32);
    }
}

__device__ __forceinline__ void build_A_from_hpack(char* smem, const uint32_t* src_rows,
                                                   int tid) {
    uint16_t* aH = (uint16_t*)(smem + HL_AH);
    uint16_t* aL = (uint16_t*)(smem + HL_AL);
    int e = tid >> 1, half = tid & 1;
    const uint4* p = (const uint4*)(src_rows) + half * 16;
    #pragma unroll 4
    for (int j0 = 0; j0 < 64; j0 += 8) {
        uint4 v0 = p[j0 >> 2], v1 = p[(j0 >> 2) + 1];
        uint4 h4, l4;
        h4.x = (v0.x & 0xFFFFu) | (v0.y << 16);  l4.x = (v0.x >> 16) | (v0.y & 0xFFFF0000u);
        h4.y = (v0.z & 0xFFFFu) | (v0.w << 16);  l4.y = (v0.z >> 16) | (v0.w & 0xFFFF0000u);
        h4.z = (v1.x & 0xFFFFu) | (v1.y << 16);  l4.z = (v1.x >> 16) | (v1.y & 0xFFFF0000u);
        h4.w = (v1.z & 0xFFFFu) | (v1.w << 16);  l4.w = (v1.z >> 16) | (v1.w & 0xFFFF0000u);
        int o = e * SA2 + half * 64 + j0;
        *(uint4*)(aH + o) = h4;
        *(uint4*)(aL + o) = l4;
    }
}

// ======== hi-only machinery (edge kernel) ========
__device__ __forceinline__ void issue_chunk_e(uint32_t sb, int buf,
                                              const uint32_t* gHi, int kb) {
    int tid = threadIdx.x;
    #pragma unroll
    for (int j = 0; j < 2; j++) {
        int g = tid + 256 * j;
        int n = (g >> 2) & 127;
        int q = g & 3;
        const uint32_t* src = gHi + n * 64 + (kb >> 1) + q * 4;
        uint32_t dst = sb + E_OFFB + (uint32_t)buf * B_CH_ST
                     + (uint32_t)(n * 20 + q * 4) * 4u;
        cp16(dst, src);
    }
    cp_commit();
}

__device__ __forceinline__ void mma_step_e(uint32_t aBase, int kb,
                                           uint32_t bBase, int kloc,
                                           int warpM, int warpN, int lane,
                                           float acc[2][8][4]) {
    uint32_t ah[2][4];
    const uint32_t arow = (uint32_t)(warpM * 32 + (lane & 15));
    const uint32_t aoff = (uint32_t)(kb + ((lane >> 4) << 3)) * 2u;
    #pragma unroll
    for (int mt = 0; mt < 2; mt++) {
        uint32_t ad = (arow + (uint32_t)(mt * 16)) * (SA2 * 2u) + aoff;
        ldsm4(ah[mt], aBase + ad);
    }
    const uint32_t nrow = (uint32_t)(warpN * 64 + (lane & 7) + ((lane >> 4) << 3));
    const uint32_t boffk = (uint32_t)((kloc >> 1) + ((lane >> 3) & 1) * 4) * 4u;
    #pragma unroll
    for (int p = 0; p < 4; p++) {
        uint32_t bh[4];
        uint32_t bd = (nrow + (uint32_t)(p * 16)) * 80u + boffk;
        ldsm4(bh, bBase + bd);
        int nt0 = p * 2, nt1 = p * 2 + 1;
        #pragma unroll
        for (int mt = 0; mt < 2; mt++) {
            MMAH(acc[mt][nt0], ah[mt], bh[0], bh[1]);
            MMAH(acc[mt][nt1], ah[mt], bh[2], bh[3]);
        }
    }
}

__device__ __forceinline__ void gemm_loop_e(uint32_t sb,
    const uint32_t* gHi, const uint32_t* nHi,
    int warpM, int warpN, int lane, float acc[2][8][4]) {
    const uint32_t aB = sb + MH;
    for (int c = 0; c < 4; c++) {
        wg1();
        __syncthreads();
        uint32_t bB = sb + E_OFFB + (uint32_t)(c & 1) * B_CH_ST;
        mma_step_e(aB, c * 32,      bB, 0,  warpM, warpN, lane, acc);
        mma_step_e(aB, c * 32 + 16, bB, 16, warpM, warpN, lane, acc);
        __syncthreads();
        if (c < 2) issue_chunk_e(sb, c & 1, gHi, (c + 2) * 32);
        else       issue_chunk_e(sb, c & 1, nHi, (c - 2) * 32);
    }
}

__device__ __forceinline__ void gemm_loop_e_scatter(uint32_t sb,
    const uint32_t* gHi,
    int warpM, int warpN, int lane,
    const uint16_t* mh, const int* s_row, int eb,
    float* m_out, float* agg, float acc[2][8][4]) {
    const uint32_t aB = sb + MH;
    const int tid = threadIdx.x;
    for (int c = 0; c < 4; c++) {
        if (c == 3) wg0(); else wg1();
        __syncthreads();
        uint32_t bB = sb + E_OFFB + (uint32_t)(c & 1) * B_CH_ST;
        mma_step_e(aB, c * 32,      bB, 0,  warpM, warpN, lane, acc);
        mma_step_e(aB, c * 32 + 16, bB, 16, warpM, warpN, lane, acc);
        __syncthreads();
        if (c < 2) issue_chunk_e(sb, c & 1, gHi, (c + 2) * 32);
        #pragma unroll
        for (int it = 0; it < 4; it++) {
            int i = tid + it * 256;
            int e = c * 32 + (i >> 5);
            int q = (i & 31) * 4;
            uint2 hh = *(const uint2*)(mh + e * SA2 + q);
            float v0 = h2f((unsigned short)(hh.x & 0xFFFFu));
            float v1 = h2f((unsigned short)(hh.x >> 16));
            float v2 = h2f((unsigned short)(hh.y & 0xFFFFu));
            float v3 = h2f((unsigned short)(hh.y >> 16));
            *(float4*)(m_out + (size_t)(eb + e) * 128 + q) = make_float4(v0, v1, v2, v3);
            red4(agg + (size_t)s_row[e] * 128 + q, v0, v1, v2, v3);
        }
    }
}

// ---------------- H1 precompute kernel ----------------
__global__ void __launch_bounds__(256, 2) h1_kernel() {
    char* smem = dynsmem;
    const uint32_t sb = smem_u32(smem);
    const int tid = threadIdx.x;
    const int lane = tid & 31, wid = tid >> 5;
    const int warpM = wid & 3, warpN = wid >> 2;
    const int gr = lane >> 2, ci = lane & 3;
    const int nb = blockIdx.x * 128;

    {
        int e = tid >> 1;
        int node = nb + e; if (node >= NN) node = NN - 1;
        build_A_from_hpack(smem, g_hpack + (size_t)node * 128, tid);
    }
    issue_chunk_hl(sb, 0, g_W1ahi, g_W1alo, 0);
    issue_chunk_hl(sb, 1, g_W1ahi, g_W1alo, 32);

    float acc[2][8][4];
    #pragma unroll
    for (int a = 0; a < 2; a++)
        #pragma unroll
        for (int b = 0; b < 8; b++)
            #pragma unroll
            for (int d = 0; d < 4; d++) acc[a][b][d] = 0.0f;

    gemm_loop_hl(sb, g_W1ahi, g_W1alo, g_W1bhi, g_W1blo, false, warpM, warpN, lane, acc);
    #pragma unroll
    for (int mt = 0; mt < 2; mt++) {
        int row = nb + warpM * 32 + mt * 16 + gr;
        #pragma unroll
        for (int nt = 0; nt < 8; nt++) {
            int c = warpN * 64 + nt * 8 + ci * 2;
            if (row < NN)
                *(float2*)(g_H1a + (size_t)row * 128 + c) = make_float2(acc[mt][nt][0], acc[mt][nt][1]);
            if (row + 8 < NN)
                *(float2*)(g_H1a + (size_t)(row + 8) * 128 + c) = make_float2(acc[mt][nt][2], acc[mt][nt][3]);
            acc[mt][nt][0] = acc[mt][nt][1] = acc[mt][nt][2] = acc[mt][nt][3] = 0.0f;
        }
    }
    gemm_loop_hl(sb, g_W1bhi, g_W1blo, nullptr, nullptr, true, warpM, warpN, lane, acc);
    #pragma unroll
    for (int mt = 0; mt < 2; mt++) {
        int row = nb + warpM * 32 + mt * 16 + gr;
        #pragma unroll
        for (int nt = 0; nt < 8; nt++) {
            int c = warpN * 64 + nt * 8 + ci * 2;
            if (row < NN)
                *(float2*)(g_H1b + (size_t)row * 128 + c) = make_float2(acc[mt][nt][0], acc[mt][nt][1]);
            if (row + 8 < NN)
                *(float2*)(g_H1b + (size_t)(row + 8) * 128 + c) = make_float2(acc[mt][nt][2], acc[mt][nt][3]);
        }
    }
}

// ---------------- node MMA kernel ----------------
__global__ void __launch_bounds__(256, 2) node_kernel(
    const float* __restrict__ coord,
    const float* __restrict__ bn1, const float* __restrict__ bn2,
    const float* __restrict__ agg, const float* __restrict__ cs4,
    float* __restrict__ h_out, float* __restrict__ c_out)
{
    char* smem = dynsmem;
    const uint32_t sb = smem_u32(smem);
    const int tid = threadIdx.x;
    const int lane = tid & 31, wid = tid >> 5;
    const int warpM = wid & 3, warpN = wid >> 2;
    const int gr = lane >> 2, ci = lane & 3;
    const int nb = blockIdx.x * 128;

    uint16_t* aH = (uint16_t*)(smem + HL_AH);
    uint16_t* aL = (uint16_t*)(smem + HL_AL);
    float* sbias = (float*)(smem + HL_BIAS);

    if (tid < 128) { sbias[tid] = bn1[tid]; sbias[128 + tid] = bn2[tid]; }

    {
        int e = tid >> 1;
        int node = nb + e; if (node >= NN) node = NN - 1;
        build_A_from_hpack(smem, g_hpack + (size_t)node * 128, tid);
    }
    issue_chunk_hl(sb, 0, g_Wn1ahi, g_Wn1alo, 0);
    issue_chunk_hl(sb, 1, g_Wn1ahi, g_Wn1alo, 32);

    float acc[2][8][4];
    #pragma unroll
    for (int a = 0; a < 2; a++)
        #pragma unroll
        for (int b = 0; b < 8; b++)
            #pragma unroll
            for (int d = 0; d < 4; d++) acc[a][b][d] = 0.0f;

    gemm_loop_hl(sb, g_Wn1ahi, g_Wn1alo, g_Wn1bhi, g_Wn1blo, false, warpM, warpN, lane, acc);

    {
        int e = tid >> 1, half = tid & 1;
        int node = nb + e; if (node >= NN) node = NN - 1;
        const float4* p = (const float4*)(agg + (size_t)node * 128 + half * 64);
        #pragma unroll 4
        for (int j0 = 0; j0 < 64; j0 += 4) {
            float4 v = p[j0 >> 2];
            unsigned short h0 = f2h(v.x), h1 = f2h(v.y), h2 = f2h(v.z), h3 = f2h(v.w);
            uint2 hp2, lp2;
            hp2.x = (uint32_t)h0 | ((uint32_t)h1 << 16);
            hp2.y = (uint32_t)h2 | ((uint32_t)h3 << 16);
            lp2.x = (uint32_t)f2h(v.x - h2f(h0)) | ((uint32_t)f2h(v.y - h2f(h1)) << 16);
            lp2.y = (uint32_t)f2h(v.z - h2f(h2)) | ((uint32_t)f2h(v.w - h2f(h3)) << 16);
            int o = e * SA2 + half * 64 + j0;
            *(uint2*)(aH + o) = hp2;
            *(uint2*)(aL + o) = lp2;
        }
    }
    __syncthreads();

    gemm_loop_hl(sb, g_Wn1bhi, g_Wn1blo, g_Wn2hi, g_Wn2lo, false, warpM, warpN, lane, acc);

    #pragma unroll
    for (int mt = 0; mt < 2; mt++) {
        int r0 = warpM * 32 + mt * 16 + gr, r1 = r0 + 8;
        #pragma unroll
        for (int nt = 0; nt < 8; nt++) {
            int c = warpN * 64 + nt * 8 + ci * 2;
            float b0 = sbias[c], b1 = sbias[c + 1];
            float x0 = silu_f(acc[mt][nt][0] + b0), x1 = silu_f(acc[mt][nt][1] + b1);
            float x2 = silu_f(acc[mt][nt][2] + b0), x3 = silu_f(acc[mt][nt][3] + b1);
            unsigned short h0 = f2h(x0), h1 = f2h(x1), h2 = f2h(x2), h3 = f2h(x3);
            *(uint32_t*)(aH + r0 * SA2 + c) = (uint32_t)h0 | ((uint32_t)h1 << 16);
            *(uint32_t*)(aL + r0 * SA2 + c) =
                (uint32_t)f2h(x0 - h2f(h0)) | ((uint32_t)f2h(x1 - h2f(h1)) << 16);
            *(uint32_t*)(aH + r1 * SA2 + c) = (uint32_t)h2 | ((uint32_t)h3 << 16);
            *(uint32_t*)(aL + r1 * SA2 + c) =
                (uint32_t)f2h(x2 - h2f(h2)) | ((uint32_t)f2h(x3 - h2f(h3)) << 16);
            acc[mt][nt][0] = acc[mt][nt][1] = acc[mt][nt][2] = acc[mt][nt][3] = 0.0f;
        }
    }
    __syncthreads();

    gemm_loop_hl(sb, g_Wn2hi, g_Wn2lo, nullptr, nullptr, true, warpM, warpN, lane, acc);

    #pragma unroll
    for (int mt = 0; mt < 2; mt++) {
        int row = nb + warpM * 32 + mt * 16 + gr;
        #pragma unroll
        for (int nt = 0; nt < 8; nt++) {
            int c = warpN * 64 + nt * 8 + ci * 2;
            float b0 = sbias[128 + c], b1 = sbias[128 + c + 1];
            if (row < NN)
                *(float2*)(h_out + (size_t)row * 128 + c) =
                    make_float2(acc[mt][nt][0] + b0, acc[mt][nt][1] + b1);
            if (row + 8 < NN)
                *(float2*)(h_out + (size_t)(row + 8) * 128 + c) =
                    make_float2(acc[mt][nt][2] + b0, acc[mt][nt][3] + b1);
        }
    }

    if (tid < 128) {
        int node = nb + tid;
        if (node < NN) {
            float4 s = *(const float4*)(cs4 + (size_t)node * 4);
            float dn = fmaxf(s.w, 1.0f);
            c_out[node * 3 + 0] = coord[node * 3 + 0] + s.x / dn;
            c_out[node * 3 + 1] = coord[node * 3 + 1] + s.y / dn;
            c_out[node * 3 + 2] = coord[node * 3 + 2] + s.z / dn;
        }
    }
}

// ---------------- edge kernel ----------------
__global__ void __launch_bounds__(256, 2) edge_kernel(
    const float* __restrict__ coord, const float* __restrict__ eattr,
    const int* __restrict__ ei, const float* __restrict__ We1,
    const float* __restrict__ be1, const float* __restrict__ be2,
    const float* __restrict__ bc1, const float* __restrict__ Wc2,
    const float* __restrict__ bc2,
    float* __restrict__ m_out, float* __restrict__ agg, float* __restrict__ cs4)
{
    char* smem = dynsmem;
    const uint32_t sb = smem_u32(smem);
    const int tid = threadIdx.x;
    const int lane = tid & 31, wid = tid >> 5;
    const int warpM = wid & 3, warpN = wid >> 2;
    const int gr = lane >> 2, ci = lane & 3;
    const int eb = blockIdx.x * 128;

    uint16_t* mh  = (uint16_t*)(smem + MH);
    float* w1c    = (float*)(smem + OFF_W1C);
    float* sbias  = (float*)(smem + OFF_BIAS);
    int* s_row    = (int*)(smem + OFF_ROW);
    int* s_col    = (int*)(smem + OFF_COL);
    float* s_dx   = (float*)(smem + OFF_D);
    float* s_dy   = s_dx + 128;
    float* s_dz   = s_dx + 256;
    float* s_rad  = (float*)(smem + OFF_RAD);
    float* s_wsum = (float*)(smem + OFF_WSUM);
    float* s_eatt = (float*)(smem + OFF_EATT);

    for (int i = tid; i < 17 * 128; i += 256) w1c[i] = We1[256 * 128 + i];
    if (tid < 128) {
        sbias[tid] = be1[tid]; sbias[128 + tid] = be2[tid];
        sbias[256 + tid] = bc1[tid]; sbias[384 + tid] = Wc2[tid];
        s_wsum[tid] = 0.0f;
    }
    if (tid == 0) *(float*)(smem + OFF_BC2) = bc2[0];
    // stage eattr [128][16] (contiguous)
    {
        const float4* src = (const float4*)(eattr + (size_t)eb * 16);
        float4* dst = (float4*)s_eatt;
        dst[tid] = src[tid];
        dst[tid + 256] = src[tid + 256];
    }
    if (tid < 128) {
        int g = eb + tid;
        int r = ei[g], c = ei[NE + g];
        s_row[tid] = r; s_col[tid] = c;
        float dx = coord[r * 3 + 0] - coord[c * 3 + 0];
        float dy = coord[r * 3 + 1] - coord[c * 3 + 1];
        float dz = coord[r * 3 + 2] - coord[c * 3 + 2];
        s_dx[tid] = dx; s_dy[tid] = dy; s_dz[tid] = dz;
        s_rad[tid] = dx * dx + dy * dy + dz * dz;
    }
    issue_chunk_e(sb, 0, g_W2hi, 0);
    issue_chunk_e(sb, 1, g_W2hi, 32);
    __syncthreads();

    // pre phase: warp-per-edge coalesced gather + m1 compute -> fp16 mh
    {
        const int w = wid, q = lane;
        const float4* w4 = (const float4*)w1c;
        #pragma unroll 2
        for (int i = 0; i < 16; i++) {
            int e = w * 16 + i;
            int r = s_row[e], c = s_col[e];
            float4 va = *(const float4*)(g_H1a + (size_t)r * 128 + q * 4);
            float4 vb = *(const float4*)(g_H1b + (size_t)c * 128 + q * 4);
            int cc0 = q * 4;
            float p0 = va.x + vb.x + sbias[cc0 + 0];
            float p1 = va.y + vb.y + sbias[cc0 + 1];
            float p2 = va.z + vb.z + sbias[cc0 + 2];
            float p3 = va.w + vb.w + sbias[cc0 + 3];
            float rad = s_rad[e];
            float4 wv = w4[q];
            p0 = fmaf(rad, wv.x, p0); p1 = fmaf(rad, wv.y, p1);
            p2 = fmaf(rad, wv.z, p2); p3 = fmaf(rad, wv.w, p3);
            #pragma unroll
            for (int j = 0; j < 16; j++) {
                float xj = s_eatt[e * 16 + j];
                float4 wj = w4[(j + 1) * 32 + q];
                p0 = fmaf(xj, wj.x, p0); p1 = fmaf(xj, wj.y, p1);
                p2 = fmaf(xj, wj.z, p2); p3 = fmaf(xj, wj.w, p3);
            }
            float s0 = silu_f(p0), s1 = silu_f(p1), s2 = silu_f(p2), s3 = silu_f(p3);
            uint2 out;
            out.x = (uint32_t)f2h(s0) | ((uint32_t)f2h(s1) << 16);
            out.y = (uint32_t)f2h(s2) | ((uint32_t)f2h(s3) << 16);
            *(uint2*)(mh + e * SA2 + cc0) = out;
        }
    }

    float acc[2][8][4];
    #pragma unroll
    for (int a = 0; a < 2; a++)
        #pragma unroll
        for (int b = 0; b < 8; b++)
            #pragma unroll
            for (int d = 0; d < 4; d++) acc[a][b][d] = 0.0f;

    gemm_loop_e(sb, g_W2hi, g_W3hi, warpM, warpN, lane, acc);

    #pragma unroll
    for (int mt = 0; mt < 2; mt++) {
        int e0 = warpM * 32 + mt * 16 + gr, e1 = e0 + 8;
        #pragma unroll
        for (int nt = 0; nt < 8; nt++) {
            int c = warpN * 64 + nt * 8 + ci * 2;
            float b0 = sbias[128 + c], b1 = sbias[128 + c + 1];
            float x0 = silu_f(acc[mt][nt][0] + b0), x1 = silu_f(acc[mt][nt][1] + b1);
            float x2 = silu_f(acc[mt][nt][2] + b0), x3 = silu_f(acc[mt][nt][3] + b1);
            *(uint32_t*)(mh + e0 * SA2 + c) = (uint32_t)f2h(x0) | ((uint32_t)f2h(x1) << 16);
            *(uint32_t*)(mh + e1 * SA2 + c) = (uint32_t)f2h(x2) | ((uint32_t)f2h(x3) << 16);
            acc[mt][nt][0] = acc[mt][nt][1] = acc[mt][nt][2] = acc[mt][nt][3] = 0.0f;
        }
    }
    __syncthreads();

    gemm_loop_e_scatter(sb, g_W3hi, warpM, warpN, lane,
                        mh, s_row, eb, m_out, agg, acc);

    {
        float part[2][2] = {{0.f, 0.f}, {0.f, 0.f}};
        #pragma unroll
        for (int mt = 0; mt < 2; mt++)
            #pragma unroll
            for (int nt = 0; nt < 8; nt++) {
                int c = warpN * 64 + nt * 8 + ci * 2;
                float b0 = sbias[256 + c], b1 = sbias[256 + c + 1];
                float w0 = sbias[384 + c], w1 = sbias[384 + c + 1];
                part[mt][0] += silu_f(acc[mt][nt][0] + b0) * w0 + silu_f(acc[mt][nt][1] + b1) * w1;
                part[mt][1] += silu_f(acc[mt][nt][2] + b0) * w0 + silu_f(acc[mt][nt][3] + b1) * w1;
            }
        #pragma unroll
        for (int off = 1; off <= 2; off <<= 1) {
            #pragma unroll
            for (int mt = 0; mt < 2; mt++) {
                part[mt][0] += __shfl_xor_sync(0xFFFFFFFFu, part[mt][0], off);
                part[mt][1] += __shfl_xor_sync(0xFFFFFFFFu, part[mt][1], off);
            }
        }
        if (ci == 0) {
            #pragma unroll
            for (int mt = 0; mt < 2; mt++) {
                int r0 = warpM * 32 + mt * 16 + gr;
                atomicAdd(&s_wsum[r0], part[mt][0]);
                atomicAdd(&s_wsum[r0 + 8], part[mt][1]);
            }
        }
    }
    __syncthreads();

    if (tid < 128) {
        float w = s_wsum[tid] + *(float*)(smem + OFF_BC2);
        int r = s_row[tid];
        red4(cs4 + (size_t)r * 4, s_dx[tid] * w, s_dy[tid] * w, s_dz[tid] * w, 1.0f);
    }
}

extern "C" void kernel_launch(void* const* d_in, const int* in_sizes, int n_in,
                              void* d_out, int out_size)
{
    const float* h     = (const float*)d_in[0];
    const float* coord = (const float*)d_in[1];
    const float* eattr = (const float*)d_in[2];
    const int*   ei    = (const int*)d_in[3];
    const float* We1 = (const float*)d_in[4];
    const float* be1 = (const float*)d_in[5];
    const float* We2 = (const float*)d_in[6];
    const float* be2 = (const float*)d_in[7];
    const float* Wn1 = (const float*)d_in[8];
    const float* bn1 = (const float*)d_in[9];
    const float* Wn2 = (const float*)d_in[10];
    const float* bn2 = (const float*)d_in[11];
    const float* Wc1 = (const float*)d_in[12];
    const float* bc1 = (const float*)d_in[13];
    const float* Wc2 = (const float*)d_in[14];
    const float* bc2 = (const float*)d_in[15];

    float* out   = (float*)d_out;
    float* h_out = out;
    float* c_out = out + (size_t)NN * 128;
    float* m_out = c_out + (size_t)NN * 3;

    void *p_agg, *p_cs4;
    cudaGetSymbolAddress(&p_agg, g_agg);
    cudaGetSymbolAddress(&p_cs4, g_cs4);
    cudaMemsetAsync(p_agg, 0, (size_t)NN * 128 * sizeof(float), 0);
    cudaMemsetAsync(p_cs4, 0, (size_t)NN * 4 * sizeof(float), 0);

    prep_h_kernel<<<(NN * 128 + 255) / 256, 256>>>(h);
    prep_w_kernel<<<224, 256>>>(We1, We2, Wc1, Wn1, Wn2);

    cudaFuncSetAttribute(h1_kernel, cudaFuncAttributeMaxDynamicSharedMemorySize, HL_SMEM);
    cudaFuncSetAttribute(node_kernel, cudaFuncAttributeMaxDynamicSharedMemorySize, HL_SMEM);
    cudaFuncSetAttribute(edge_kernel, cudaFuncAttributeMaxDynamicSharedMemorySize, EDGE_SMEM);

    h1_kernel<<<(NN + 127) / 128, 256, HL_SMEM>>>();

    edge_kernel<<<NE / 128, 256, EDGE_SMEM>>>(
        coord, eattr, ei, We1, be1, be2, bc1, Wc2, bc2,
        m_out, (float*)p_agg, (float*)p_cs4);

    node_kernel<<<(NN + 127) / 128, 256, HL_SMEM>>>(
        coord, bn1, bn2, (const float*)p_agg, (const float*)p_cs4, h_out, c_out);
}

// round 17
// speedup vs baseline: 1.8558x; 1.1119x over previous
#include <cuda_runtime.h>
#include <cuda_fp16.h>
#include <stdint.h>

#define NN 50000
#define NE 800000

// ---------------- device scratch ----------------
__device__ float g_agg[(size_t)NN * 128];
__device__ float g_cs4[(size_t)NN * 4];
__device__ float g_H1a[(size_t)NN * 128];
__device__ float g_H1b[(size_t)NN * 128];
__device__ uint32_t g_hpack[(size_t)NN * 128];   // (lo16<<16)|hi16 fp16 split of h
__device__ uint32_t g_W1ahi[128 * 64], g_W1alo[128 * 64];
__device__ uint32_t g_W1bhi[128 * 64], g_W1blo[128 * 64];
__device__ uint32_t g_W2hi[128 * 64];
__device__ uint32_t g_W3hi[128 * 64];
__device__ uint32_t g_Wn1ahi[128 * 64], g_Wn1alo[128 * 64];
__device__ uint32_t g_Wn1bhi[128 * 64], g_Wn1blo[128 * 64];
__device__ uint32_t g_Wn2hi[128 * 64],  g_Wn2lo[128 * 64];

__device__ __forceinline__ unsigned short f2h(float x) {
    __half v = __float2half(x);
    return *reinterpret_cast<unsigned short*>(&v);
}
__device__ __forceinline__ float h2f(unsigned short u) {
    __half v = *reinterpret_cast<__half*>(&u);
    return __half2float(v);
}
__device__ __forceinline__ float silu_f(float x) { return x / (1.0f + __expf(-x)); }
__device__ __forceinline__ void red4(float* p, float a, float b, float c, float d) {
    asm volatile("red.global.add.v4.f32 [%0], {%1,%2,%3,%4};"
                 :: "l"(p), "f"(a), "f"(b), "f"(c), "f"(d) : "memory");
}
__device__ __forceinline__ uint32_t smem_u32(const void* p) {
    uint32_t a;
    asm("{ .reg .u64 t; cvta.to.shared.u64 t, %1; cvt.u32.u64 %0, t; }" : "=r"(a) : "l"(p));
    return a;
}
__device__ __forceinline__ void cp16(uint32_t dst, const void* src) {
    asm volatile("cp.async.ca.shared.global [%0], [%1], 16;" :: "r"(dst), "l"(src));
}
__device__ __forceinline__ void cp_commit() {
    asm volatile("cp.async.commit_group;" ::: "memory");
}
__device__ __forceinline__ void wg0() { asm volatile("cp.async.wait_group 0;" ::: "memory"); }
__device__ __forceinline__ void wg1() { asm volatile("cp.async.wait_group 1;" ::: "memory"); }
__device__ __forceinline__ void ldsm4(uint32_t* r, uint32_t addr) {
    asm volatile("ldmatrix.sync.aligned.m8n8.x4.shared.b16 {%0,%1,%2,%3}, [%4];"
        : "=r"(r[0]), "=r"(r[1]), "=r"(r[2]), "=r"(r[3]) : "r"(addr));
}
#define MMAH(ac, a, b0, b1) \
    asm volatile("mma.sync.aligned.m16n8k16.row.col.f32.f16.f16.f32 " \
        "{%0,%1,%2,%3}, {%4,%5,%6,%7}, {%8,%9}, {%0,%1,%2,%3};" \
        : "+f"((ac)[0]), "+f"((ac)[1]), "+f"((ac)[2]), "+f"((ac)[3]) \
        : "r"((a)[0]), "r"((a)[1]), "r"((a)[2]), "r"((a)[3]), "r"(b0), "r"(b1))

#define SA2 136
#define B_CH_ST  10240u
// ---- edge smem layout ----
#define MH        0u
#define E_OFFB    34816u
#define OFF_W1C   55296u
#define OFF_BIAS  64000u
#define OFF_ROW   66048u
#define OFF_COL   66560u
#define OFF_D     67072u
#define OFF_RAD   68608u
#define OFF_WSUM  69120u
#define OFF_BC2   69632u
#define OFF_EATT  69664u      // [128][16] f32 = 8192
#define EDGE_SMEM 77856u
// ---- hi/lo GEMM smem layout (h1 + node kernels) ----
#define HL_AH     0u
#define HL_AL     34816u
#define HL_OFFB   69632u
#define HL_BUF_ST 20480u
#define HL_BIAS   110592u
#define HL_SMEM   111616u

extern __shared__ char dynsmem[];

// ---------------- prep ----------------
__global__ void prep_h_kernel(const float* __restrict__ h) {
    size_t i = (size_t)blockIdx.x * 256 + threadIdx.x;
    if (i < (size_t)NN * 128) {
        float v = h[i];
        unsigned short hi = f2h(v);
        unsigned short lo = f2h(v - h2f(hi));
        g_hpack[i] = (uint32_t)hi | ((uint32_t)lo << 16);
    }
}
__global__ void prep_w_kernel(const float* __restrict__ We1,
                              const float* __restrict__ We2,
                              const float* __restrict__ Wc1,
                              const float* __restrict__ Wn1,
                              const float* __restrict__ Wn2) {
    int t = blockIdx.x * 256 + threadIdx.x;
    if (t >= 57344) return;
    int img = t >> 13, u = t & 8191, n = u >> 6, kp = u & 63;
    int k0 = kp * 2, k1 = k0 + 1;
    float v0, v1;
    if (img == 0)      { v0 = We1[k0 * 128 + n];         v1 = We1[k1 * 128 + n]; }
    else if (img == 1) { v0 = We1[(128 + k0) * 128 + n]; v1 = We1[(128 + k1) * 128 + n]; }
    else if (img == 2) { v0 = We2[k0 * 128 + n];         v1 = We2[k1 * 128 + n]; }
    else if (img == 3) { v0 = Wc1[k0 * 128 + n];         v1 = Wc1[k1 * 128 + n]; }
    else if (img == 4) { v0 = Wn1[k0 * 128 + n];         v1 = Wn1[k1 * 128 + n]; }
    else if (img == 5) { v0 = Wn1[(128 + k0) * 128 + n]; v1 = Wn1[(128 + k1) * 128 + n]; }
    else               { v0 = Wn2[k0 * 128 + n];         v1 = Wn2[k1 * 128 + n]; }
    unsigned short h0 = f2h(v0), h1 = f2h(v1);
    uint32_t hpack = (uint32_t)h0 | ((uint32_t)h1 << 16);
    uint32_t lpack = (uint32_t)f2h(v0 - h2f(h0)) | ((uint32_t)f2h(v1 - h2f(h1)) << 16);
    int o = n * 64 + kp;
    if (img == 0)      { g_W1ahi[o] = hpack; g_W1alo[o] = lpack; }
    else if (img == 1) { g_W1bhi[o] = hpack; g_W1blo[o] = lpack; }
    else if (img == 2) { g_W2hi[o] = hpack; }
    else if (img == 3) { g_W3hi[o] = hpack; }
    else if (img == 4) { g_Wn1ahi[o] = hpack; g_Wn1alo[o] = lpack; }
    else if (img == 5) { g_Wn1bhi[o] = hpack; g_Wn1blo[o] = lpack; }
    else               { g_Wn2hi[o] = hpack; g_Wn2lo[o] = lpack; }
}

// ======== hi+lo GEMM machinery ========
__device__ __forceinline__ void issue_chunk_hl(uint32_t sb, int buf,
                                               const uint32_t* gHi, const uint32_t* gLo, int kb) {
    int tid = threadIdx.x;
    #pragma unroll
    for (int j = 0; j < 4; j++) {
        int g = tid + 256 * j;
        int arr = g >> 9;
        int n = (g >> 2) & 127;
        int q = g & 3;
        const uint32_t* src = (arr ? gLo : gHi) + n * 64 + (kb >> 1) + q * 4;
        uint32_t dst = sb + HL_OFFB + (uint32_t)buf * HL_BUF_ST + (uint32_t)arr * B_CH_ST
                     + (uint32_t)(n * 20 + q * 4) * 4u;
        cp16(dst, src);
    }
    cp_commit();
}

__device__ __forceinline__ void mma_step_hl(uint32_t aBaseH, uint32_t aBaseL,
                                            int kb, uint32_t bBase, int kloc,
                                            int warpM, int warpN, int lane,
                                            float acc[2][8][4]) {
    uint32_t ah[2][4], al[2][4];
    const uint32_t arow = (uint32_t)(warpM * 32 + (lane & 15));
    const uint32_t aoff = (uint32_t)(kb + ((lane >> 4) << 3)) * 2u;
    #pragma unroll
    for (int mt = 0; mt < 2; mt++) {
        uint32_t ad = (arow + (uint32_t)(mt * 16)) * (SA2 * 2u) + aoff;
        ldsm4(ah[mt], aBaseH + ad);
        ldsm4(al[mt], aBaseL + ad);
    }
    const uint32_t nrow = (uint32_t)(warpN * 64 + (lane & 7) + ((lane >> 4) << 3));
    const uint32_t boffk = (uint32_t)((kloc >> 1) + ((lane >> 3) & 1) * 4) * 4u;
    #pragma unroll
    for (int p = 0; p < 4; p++) {
        uint32_t bh[4], bl[4];
        uint32_t bd = (nrow + (uint32_t)(p * 16)) * 80u + boffk;
        ldsm4(bh, bBase + bd);
        ldsm4(bl, bBase + B_CH_ST + bd);
        int nt0 = p * 2, nt1 = p * 2 + 1;
        #pragma unroll
        for (int mt = 0; mt < 2; mt++) {
            MMAH(acc[mt][nt0], ah[mt], bh[0], bh[1]);
            MMAH(acc[mt][nt0], ah[mt], bl[0], bl[1]);
            MMAH(acc[mt][nt0], al[mt], bh[0], bh[1]);
            MMAH(acc[mt][nt1], ah[mt], bh[2], bh[3]);
            MMAH(acc[mt][nt1], ah[mt], bl[2], bl[3]);
            MMAH(acc[mt][nt1], al[mt], bh[2], bh[3]);
        }
    }
}

__device__ __forceinline__ void gemm_loop_hl(uint32_t sb,
    const uint32_t* gHi, const uint32_t* gLo,
    const uint32_t* nHi, const uint32_t* nLo, bool last,
    int warpM, int warpN, int lane, float acc[2][8][4]) {
    const uint32_t aH = sb + HL_AH, aL = sb + HL_AL;
    for (int c = 0; c < 4; c++) {
        if (c == 3 && last) wg0(); else wg1();
        __syncthreads();
        uint32_t bB = sb + HL_OFFB + (uint32_t)(c & 1) * HL_BUF_ST;
        mma_step_hl(aH, aL, c * 32,      bB, 0,  warpM, warpN, lane, acc);
        mma_step_hl(aH, aL, c * 32 + 16, bB, 16, warpM, warpN, lane, acc);
        __syncthreads();
        if (c < 2)      issue_chunk_hl(sb, c & 1, gHi, gLo, (c + 2) * 32);
        else if (!last) issue_chunk_hl(sb, c & 1, nHi, nLo, (c - 2) * 32);
    }
}

__device__ __forceinline__ void build_A_from_hpack(char* smem, const uint32_t* src_rows,
                                                   int tid) {
    uint16_t* aH = (uint16_t*)(smem + HL_AH);
    uint16_t* aL = (uint16_t*)(smem + HL_AL);
    int e = tid >> 1, half = tid & 1;
    const uint4* p = (const uint4*)(src_rows) + half * 16;
    #pragma unroll 4
    for (int j0 = 0; j0 < 64; j0 += 8) {
        uint4 v0 = p[j0 >> 2], v1 = p[(j0 >> 2) + 1];
        uint4 h4, l4;
        h4.x = (v0.x & 0xFFFFu) | (v0.y << 16);  l4.x = (v0.x >> 16) | (v0.y & 0xFFFF0000u);
        h4.y = (v0.z & 0xFFFFu) | (v0.w << 16);  l4.y = (v0.z >> 16) | (v0.w & 0xFFFF0000u);
        h4.z = (v1.x & 0xFFFFu) | (v1.y << 16);  l4.z = (v1.x >> 16) | (v1.y & 0xFFFF0000u);
        h4.w = (v1.z & 0xFFFFu) | (v1.w << 16);  l4.w = (v1.z >> 16) | (v1.w & 0xFFFF0000u);
        int o = e * SA2 + half * 64 + j0;
        *(uint4*)(aH + o) = h4;
        *(uint4*)(aL + o) = l4;
    }
}

// ======== hi-only machinery (edge kernel) ========
__device__ __forceinline__ void issue_chunk_e(uint32_t sb, int buf,
                                              const uint32_t* gHi, int kb) {
    int tid = threadIdx.x;
    #pragma unroll
    for (int j = 0; j < 2; j++) {
        int g = tid + 256 * j;
        int n = (g >> 2) & 127;
        int q = g & 3;
        const uint32_t* src = gHi + n * 64 + (kb >> 1) + q * 4;
        uint32_t dst = sb + E_OFFB + (uint32_t)buf * B_CH_ST
                     + (uint32_t)(n * 20 + q * 4) * 4u;
        cp16(dst, src);
    }
    cp_commit();
}

__device__ __forceinline__ void mma_step_e(uint32_t aBase, int kb,
                                           uint32_t bBase, int kloc,
                                           int warpM, int warpN, int lane,
                                           float acc[2][8][4]) {
    uint32_t ah[2][4];
    const uint32_t arow = (uint32_t)(warpM * 32 + (lane & 15));
    const uint32_t aoff = (uint32_t)(kb + ((lane >> 4) << 3)) * 2u;
    #pragma unroll
    for (int mt = 0; mt < 2; mt++) {
        uint32_t ad = (arow + (uint32_t)(mt * 16)) * (SA2 * 2u) + aoff;
        ldsm4(ah[mt], aBase + ad);
    }
    const uint32_t nrow = (uint32_t)(warpN * 64 + (lane & 7) + ((lane >> 4) << 3));
    const uint32_t boffk = (uint32_t)((kloc >> 1) + ((lane >> 3) & 1) * 4) * 4u;
    #pragma unroll
    for (int p = 0; p < 4; p++) {
        uint32_t bh[4];
        uint32_t bd = (nrow + (uint32_t)(p * 16)) * 80u + boffk;
        ldsm4(bh, bBase + bd);
        int nt0 = p * 2, nt1 = p * 2 + 1;
        #pragma unroll
        for (int mt = 0; mt < 2; mt++) {
            MMAH(acc[mt][nt0], ah[mt], bh[0], bh[1]);
            MMAH(acc[mt][nt1], ah[mt], bh[2], bh[3]);
        }
    }
}

__device__ __forceinline__ void gemm_loop_e(uint32_t sb,
    const uint32_t* gHi, const uint32_t* nHi,
    int warpM, int warpN, int lane, float acc[2][8][4]) {
    const uint32_t aB = sb + MH;
    for (int c = 0; c < 4; c++) {
        wg1();
        __syncthreads();
        uint32_t bB = sb + E_OFFB + (uint32_t)(c & 1) * B_CH_ST;
        mma_step_e(aB, c * 32,      bB, 0,  warpM, warpN, lane, acc);
        mma_step_e(aB, c * 32 + 16, bB, 16, warpM, warpN, lane, acc);
        __syncthreads();
        if (c < 2) issue_chunk_e(sb, c & 1, gHi, (c + 2) * 32);
        else       issue_chunk_e(sb, c & 1, nHi, (c - 2) * 32);
    }
}

__device__ __forceinline__ void gemm_loop_e_scatter(uint32_t sb,
    const uint32_t* gHi,
    int warpM, int warpN, int lane,
    const uint16_t* mh, const int* s_row, int eb,
    float* m_out, float* agg, float acc[2][8][4]) {
    const uint32_t aB = sb + MH;
    const int tid = threadIdx.x;
    for (int c = 0; c < 4; c++) {
        if (c == 3) wg0(); else wg1();
        __syncthreads();
        uint32_t bB = sb + E_OFFB + (uint32_t)(c & 1) * B_CH_ST;
        mma_step_e(aB, c * 32,      bB, 0,  warpM, warpN, lane, acc);
        mma_step_e(aB, c * 32 + 16, bB, 16, warpM, warpN, lane, acc);
        __syncthreads();
        if (c < 2) issue_chunk_e(sb, c & 1, gHi, (c + 2) * 32);
        #pragma unroll
        for (int it = 0; it < 4; it++) {
            int i = tid + it * 256;
            int e = c * 32 + (i >> 5);
            int q = (i & 31) * 4;
            uint2 hh = *(const uint2*)(mh + e * SA2 + q);
            float v0 = h2f((unsigned short)(hh.x & 0xFFFFu));
            float v1 = h2f((unsigned short)(hh.x >> 16));
            float v2 = h2f((unsigned short)(hh.y & 0xFFFFu));
            float v3 = h2f((unsigned short)(hh.y >> 16));
            *(float4*)(m_out + (size_t)(eb + e) * 128 + q) = make_float4(v0, v1, v2, v3);
            red4(agg + (size_t)s_row[e] * 128 + q, v0, v1, v2, v3);
        }
    }
}

// ---------------- H1 precompute kernel ----------------
__global__ void __launch_bounds__(256, 2) h1_kernel() {
    char* smem = dynsmem;
    const uint32_t sb = smem_u32(smem);
    const int tid = threadIdx.x;
    const int lane = tid & 31, wid = tid >> 5;
    const int warpM = wid & 3, warpN = wid >> 2;
    const int gr = lane >> 2, ci = lane & 3;
    const int nb = blockIdx.x * 128;

    {
        int e = tid >> 1;
        int node = nb + e; if (node >= NN) node = NN - 1;
        build_A_from_hpack(smem, g_hpack + (size_t)node * 128, tid);
    }
    issue_chunk_hl(sb, 0, g_W1ahi, g_W1alo, 0);
    issue_chunk_hl(sb, 1, g_W1ahi, g_W1alo, 32);

    float acc[2][8][4];
    #pragma unroll
    for (int a = 0; a < 2; a++)
        #pragma unroll
        for (int b = 0; b < 8; b++)
            #pragma unroll
            for (int d = 0; d < 4; d++) acc[a][b][d] = 0.0f;

    gemm_loop_hl(sb, g_W1ahi, g_W1alo, g_W1bhi, g_W1blo, false, warpM, warpN, lane, acc);
    #pragma unroll
    for (int mt = 0; mt < 2; mt++) {
        int row = nb + warpM * 32 + mt * 16 + gr;
        #pragma unroll
        for (int nt = 0; nt < 8; nt++) {
            int c = warpN * 64 + nt * 8 + ci * 2;
            if (row < NN)
                *(float2*)(g_H1a + (size_t)row * 128 + c) = make_float2(acc[mt][nt][0], acc[mt][nt][1]);
            if (row + 8 < NN)
                *(float2*)(g_H1a + (size_t)(row + 8) * 128 + c) = make_float2(acc[mt][nt][2], acc[mt][nt][3]);
            acc[mt][nt][0] = acc[mt][nt][1] = acc[mt][nt][2] = acc[mt][nt][3] = 0.0f;
        }
    }
    gemm_loop_hl(sb, g_W1bhi, g_W1blo, nullptr, nullptr, true, warpM, warpN, lane, acc);
    #pragma unroll
    for (int mt = 0; mt < 2; mt++) {
        int row = nb + warpM * 32 + mt * 16 + gr;
        #pragma unroll
        for (int nt = 0; nt < 8; nt++) {
            int c = warpN * 64 + nt * 8 + ci * 2;
            if (row < NN)
                *(float2*)(g_H1b + (size_t)row * 128 + c) = make_float2(acc[mt][nt][0], acc[mt][nt][1]);
            if (row + 8 < NN)
                *(float2*)(g_H1b + (size_t)(row + 8) * 128 + c) = make_float2(acc[mt][nt][2], acc[mt][nt][3]);
        }
    }
}

// ---------------- node MMA kernel ----------------
__global__ void __launch_bounds__(256, 2) node_kernel(
    const float* __restrict__ coord,
    const float* __restrict__ bn1, const float* __restrict__ bn2,
    const float* __restrict__ agg, const float* __restrict__ cs4,
    float* __restrict__ h_out, float* __restrict__ c_out)
{
    char* smem = dynsmem;
    const uint32_t sb = smem_u32(smem);
    const int tid = threadIdx.x;
    const int lane = tid & 31, wid = tid >> 5;
    const int warpM = wid & 3, warpN = wid >> 2;
    const int gr = lane >> 2, ci = lane & 3;
    const int nb = blockIdx.x * 128;

    uint16_t* aH = (uint16_t*)(smem + HL_AH);
    uint16_t* aL = (uint16_t*)(smem + HL_AL);
    float* sbias = (float*)(smem + HL_BIAS);

    if (tid < 128) { sbias[tid] = bn1[tid]; sbias[128 + tid] = bn2[tid]; }

    {
        int e = tid >> 1;
        int node = nb + e; if (node >= NN) node = NN - 1;
        build_A_from_hpack(smem, g_hpack + (size_t)node * 128, tid);
    }
    issue_chunk_hl(sb, 0, g_Wn1ahi, g_Wn1alo, 0);
    issue_chunk_hl(sb, 1, g_Wn1ahi, g_Wn1alo, 32);

    float acc[2][8][4];
    #pragma unroll
    for (int a = 0; a < 2; a++)
        #pragma unroll
        for (int b = 0; b < 8; b++)
            #pragma unroll
            for (int d = 0; d < 4; d++) acc[a][b][d] = 0.0f;

    gemm_loop_hl(sb, g_Wn1ahi, g_Wn1alo, g_Wn1bhi, g_Wn1blo, false, warpM, warpN, lane, acc);

    {
        int e = tid >> 1, half = tid & 1;
        int node = nb + e; if (node >= NN) node = NN - 1;
        const float4* p = (const float4*)(agg + (size_t)node * 128 + half * 64);
        #pragma unroll 4
        for (int j0 = 0; j0 < 64; j0 += 4) {
            float4 v = p[j0 >> 2];
            unsigned short h0 = f2h(v.x), h1 = f2h(v.y), h2 = f2h(v.z), h3 = f2h(v.w);
            uint2 hp2, lp2;
            hp2.x = (uint32_t)h0 | ((uint32_t)h1 << 16);
            hp2.y = (uint32_t)h2 | ((uint32_t)h3 << 16);
            lp2.x = (uint32_t)f2h(v.x - h2f(h0)) | ((uint32_t)f2h(v.y - h2f(h1)) << 16);
            lp2.y = (uint32_t)f2h(v.z - h2f(h2)) | ((uint32_t)f2h(v.w - h2f(h3)) << 16);
            int o = e * SA2 + half * 64 + j0;
            *(uint2*)(aH + o) = hp2;
            *(uint2*)(aL + o) = lp2;
        }
    }
    __syncthreads();

    gemm_loop_hl(sb, g_Wn1bhi, g_Wn1blo, g_Wn2hi, g_Wn2lo, false, warpM, warpN, lane, acc);

    #pragma unroll
    for (int mt = 0; mt < 2; mt++) {
        int r0 = warpM * 32 + mt * 16 + gr, r1 = r0 + 8;
        #pragma unroll
        for (int nt = 0; nt < 8; nt++) {
            int c = warpN * 64 + nt * 8 + ci * 2;
            float b0 = sbias[c], b1 = sbias[c + 1];
            float x0 = silu_f(acc[mt][nt][0] + b0), x1 = silu_f(acc[mt][nt][1] + b1);
            float x2 = silu_f(acc[mt][nt][2] + b0), x3 = silu_f(acc[mt][nt][3] + b1);
            unsigned short h0 = f2h(x0), h1 = f2h(x1), h2 = f2h(x2), h3 = f2h(x3);
            *(uint32_t*)(aH + r0 * SA2 + c) = (uint32_t)h0 | ((uint32_t)h1 << 16);
            *(uint32_t*)(aL + r0 * SA2 + c) =
                (uint32_t)f2h(x0 - h2f(h0)) | ((uint32_t)f2h(x1 - h2f(h1)) << 16);
            *(uint32_t*)(aH + r1 * SA2 + c) = (uint32_t)h2 | ((uint32_t)h3 << 16);
            *(uint32_t*)(aL + r1 * SA2 + c) =
                (uint32_t)f2h(x2 - h2f(h2)) | ((uint32_t)f2h(x3 - h2f(h3)) << 16);
            acc[mt][nt][0] = acc[mt][nt][1] = acc[mt][nt][2] = acc[mt][nt][3] = 0.0f;
        }
    }
    __syncthreads();

    gemm_loop_hl(sb, g_Wn2hi, g_Wn2lo, nullptr, nullptr, true, warpM, warpN, lane, acc);

    #pragma unroll
    for (int mt = 0; mt < 2; mt++) {
        int row = nb + warpM * 32 + mt * 16 + gr;
        #pragma unroll
        for (int nt = 0; nt < 8; nt++) {
            int c = warpN * 64 + nt * 8 + ci * 2;
            float b0 = sbias[128 + c], b1 = sbias[128 + c + 1];
            if (row < NN)
                *(float2*)(h_out + (size_t)row * 128 + c) =
                    make_float2(acc[mt][nt][0] + b0, acc[mt][nt][1] + b1);
            if (row + 8 < NN)
                *(float2*)(h_out + (size_t)(row + 8) * 128 + c) =
                    make_float2(acc[mt][nt][2] + b0, acc[mt][nt][3] + b1);
        }
    }

    if (tid < 128) {
        int node = nb + tid;
        if (node < NN) {
            float4 s = *(const float4*)(cs4 + (size_t)node * 4);
            float dn = fmaxf(s.w, 1.0f);
            c_out[node * 3 + 0] = coord[node * 3 + 0] + s.x / dn;
            c_out[node * 3 + 1] = coord[node * 3 + 1] + s.y / dn;
            c_out[node * 3 + 2] = coord[node * 3 + 2] + s.z / dn;
        }
    }
}

// ---------------- edge kernel ----------------
__global__ void __launch_bounds__(256, 2) edge_kernel(
    const float* __restrict__ coord, const float* __restrict__ eattr,
    const int* __restrict__ ei, const float* __restrict__ We1,
    const float* __restrict__ be1, const float* __restrict__ be2,
    const float* __restrict__ bc1, const float* __restrict__ Wc2,
    const float* __restrict__ bc2,
    float* __restrict__ m_out, float* __restrict__ agg, float* __restrict__ cs4)
{
    char* smem = dynsmem;
    const uint32_t sb = smem_u32(smem);
    const int tid = threadIdx.x;
    const int lane = tid & 31, wid = tid >> 5;
    const int warpM = wid & 3, warpN = wid >> 2;
    const int gr = lane >> 2, ci = lane & 3;
    const int eb = blockIdx.x * 128;

    uint16_t* mh  = (uint16_t*)(smem + MH);
    float* w1c    = (float*)(smem + OFF_W1C);
    float* sbias  = (float*)(smem + OFF_BIAS);
    int* s_row    = (int*)(smem + OFF_ROW);
    int* s_col    = (int*)(smem + OFF_COL);
    float* s_dx   = (float*)(smem + OFF_D);
    float* s_dy   = s_dx + 128;
    float* s_dz   = s_dx + 256;
    float* s_rad  = (float*)(smem + OFF_RAD);
    float* s_wsum = (float*)(smem + OFF_WSUM);
    float* s_eatt = (float*)(smem + OFF_EATT);

    for (int i = tid; i < 17 * 128; i += 256) w1c[i] = We1[256 * 128 + i];
    if (tid < 128) {
        sbias[tid] = be1[tid]; sbias[128 + tid] = be2[tid];
        sbias[256 + tid] = bc1[tid]; sbias[384 + tid] = Wc2[tid];
        s_wsum[tid] = 0.0f;
    }
    if (tid == 0) *(float*)(smem + OFF_BC2) = bc2[0];
    {
        const float4* src = (const float4*)(eattr + (size_t)eb * 16);
        float4* dst = (float4*)s_eatt;
        dst[tid] = src[tid];
        dst[tid + 256] = src[tid + 256];
    }
    if (tid < 128) {
        int g = eb + tid;
        int r = ei[g], c = ei[NE + g];
        s_row[tid] = r; s_col[tid] = c;
        float dx = coord[r * 3 + 0] - coord[c * 3 + 0];
        float dy = coord[r * 3 + 1] - coord[c * 3 + 1];
        float dz = coord[r * 3 + 2] - coord[c * 3 + 2];
        s_dx[tid] = dx; s_dy[tid] = dy; s_dz[tid] = dz;
        s_rad[tid] = dx * dx + dy * dy + dz * dz;
    }
    issue_chunk_e(sb, 0, g_W2hi, 0);
    issue_chunk_e(sb, 1, g_W2hi, 32);
    __syncthreads();

    // pre phase: warp-per-edge coalesced gather (1-deep pipelined)
    // + hoisted w1c registers + m1 compute -> fp16 mh
    {
        const int w = wid, q = lane;
        const float4* w4 = (const float4*)w1c;
        float4 wreg[17];
        #pragma unroll
        for (int j = 0; j < 17; j++) wreg[j] = w4[j * 32 + q];
        const int e0 = w * 16;
        float4 va = *(const float4*)(g_H1a + (size_t)s_row[e0] * 128 + q * 4);
        float4 vb = *(const float4*)(g_H1b + (size_t)s_col[e0] * 128 + q * 4);
        float b0 = sbias[q * 4 + 0], b1 = sbias[q * 4 + 1];
        float b2 = sbias[q * 4 + 2], b3 = sbias[q * 4 + 3];
        #pragma unroll 2
        for (int i = 0; i < 16; i++) {
            int e = e0 + i;
            float4 cva = va, cvb = vb;
            if (i < 15) {
                va = *(const float4*)(g_H1a + (size_t)s_row[e + 1] * 128 + q * 4);
                vb = *(const float4*)(g_H1b + (size_t)s_col[e + 1] * 128 + q * 4);
            }
            float p0 = cva.x + cvb.x + b0;
            float p1 = cva.y + cvb.y + b1;
            float p2 = cva.z + cvb.z + b2;
            float p3 = cva.w + cvb.w + b3;
            float rad = s_rad[e];
            p0 = fmaf(rad, wreg[0].x, p0); p1 = fmaf(rad, wreg[0].y, p1);
            p2 = fmaf(rad, wreg[0].z, p2); p3 = fmaf(rad, wreg[0].w, p3);
            #pragma unroll
            for (int j = 0; j < 16; j++) {
                float xj = s_eatt[e * 16 + j];
                p0 = fmaf(xj, wreg[j + 1].x, p0); p1 = fmaf(xj, wreg[j + 1].y, p1);
                p2 = fmaf(xj, wreg[j + 1].z, p2); p3 = fmaf(xj, wreg[j + 1].w, p3);
            }
            float s0 = silu_f(p0), s1 = silu_f(p1), s2 = silu_f(p2), s3 = silu_f(p3);
            uint2 out;
            out.x = (uint32_t)f2h(s0) | ((uint32_t)f2h(s1) << 16);
            out.y = (uint32_t)f2h(s2) | ((uint32_t)f2h(s3) << 16);
            *(uint2*)(mh + e * SA2 + q * 4) = out;
        }
    }

    float acc[2][8][4];
    #pragma unroll
    for (int a = 0; a < 2; a++)
        #pragma unroll
        for (int b = 0; b < 8; b++)
            #pragma unroll
            for (int d = 0; d < 4; d++) acc[a][b][d] = 0.0f;

    gemm_loop_e(sb, g_W2hi, g_W3hi, warpM, warpN, lane, acc);

    #pragma unroll
    for (int mt = 0; mt < 2; mt++) {
        int e0 = warpM * 32 + mt * 16 + gr, e1 = e0 + 8;
        #pragma unroll
        for (int nt = 0; nt < 8; nt++) {
            int c = warpN * 64 + nt * 8 + ci * 2;
            float b0 = sbias[128 + c], b1 = sbias[128 + c + 1];
            float x0 = silu_f(acc[mt][nt][0] + b0), x1 = silu_f(acc[mt][nt][1] + b1);
            float x2 = silu_f(acc[mt][nt][2] + b0), x3 = silu_f(acc[mt][nt][3] + b1);
            *(uint32_t*)(mh + e0 * SA2 + c) = (uint32_t)f2h(x0) | ((uint32_t)f2h(x1) << 16);
            *(uint32_t*)(mh + e1 * SA2 + c) = (uint32_t)f2h(x2) | ((uint32_t)f2h(x3) << 16);
            acc[mt][nt][0] = acc[mt][nt][1] = acc[mt][nt][2] = acc[mt][nt][3] = 0.0f;
        }
    }
    __syncthreads();

    gemm_loop_e_scatter(sb, g_W3hi, warpM, warpN, lane,
                        mh, s_row, eb, m_out, agg, acc);

    {
        float part[2][2] = {{0.f, 0.f}, {0.f, 0.f}};
        #pragma unroll
        for (int mt = 0; mt < 2; mt++)
            #pragma unroll
            for (int nt = 0; nt < 8; nt++) {
                int c = warpN * 64 + nt * 8 + ci * 2;
                float b0 = sbias[256 + c], b1 = sbias[256 + c + 1];
                float w0 = sbias[384 + c], w1 = sbias[384 + c + 1];
                part[mt][0] += silu_f(acc[mt][nt][0] + b0) * w0 + silu_f(acc[mt][nt][1] + b1) * w1;
                part[mt][1] += silu_f(acc[mt][nt][2] + b0) * w0 + silu_f(acc[mt][nt][3] + b1) * w1;
            }
        #pragma unroll
        for (int off = 1; off <= 2; off <<= 1) {
            #pragma unroll
            for (int mt = 0; mt < 2; mt++) {
                part[mt][0] += __shfl_xor_sync(0xFFFFFFFFu, part[mt][0], off);
                part[mt][1] += __shfl_xor_sync(0xFFFFFFFFu, part[mt][1], off);
            }
        }
        if (ci == 0) {
            #pragma unroll
            for (int mt = 0; mt < 2; mt++) {
                int r0 = warpM * 32 + mt * 16 + gr;
                atomicAdd(&s_wsum[r0], part[mt][0]);
                atomicAdd(&s_wsum[r0 + 8], part[mt][1]);
            }
        }
    }
    __syncthreads();

    if (tid < 128) {
        float w = s_wsum[tid] + *(float*)(smem + OFF_BC2);
        int r = s_row[tid];
        red4(cs4 + (size_t)r * 4, s_dx[tid] * w, s_dy[tid] * w, s_dz[tid] * w, 1.0f);
    }
}

extern "C" void kernel_launch(void* const* d_in, const int* in_sizes, int n_in,
                              void* d_out, int out_size)
{
    const float* h     = (const float*)d_in[0];
    const float* coord = (const float*)d_in[1];
    const float* eattr = (const float*)d_in[2];
    const int*   ei    = (const int*)d_in[3];
    const float* We1 = (const float*)d_in[4];
    const float* be1 = (const float*)d_in[5];
    const float* We2 = (const float*)d_in[6];
    const float* be2 = (const float*)d_in[7];
    const float* Wn1 = (const float*)d_in[8];
    const float* bn1 = (const float*)d_in[9];
    const float* Wn2 = (const float*)d_in[10];
    const float* bn2 = (const float*)d_in[11];
    const float* Wc1 = (const float*)d_in[12];
    const float* bc1 = (const float*)d_in[13];
    const float* Wc2 = (const float*)d_in[14];
    const float* bc2 = (const float*)d_in[15];

    float* out   = (float*)d_out;
    float* h_out = out;
    float* c_out = out + (size_t)NN * 128;
    float* m_out = c_out + (size_t)NN * 3;

    void *p_agg, *p_cs4;
    cudaGetSymbolAddress(&p_agg, g_agg);
    cudaGetSymbolAddress(&p_cs4, g_cs4);
    cudaMemsetAsync(p_agg, 0, (size_t)NN * 128 * sizeof(float), 0);
    cudaMemsetAsync(p_cs4, 0, (size_t)NN * 4 * sizeof(float), 0);

    prep_h_kernel<<<(NN * 128 + 255) / 256, 256>>>(h);
    prep_w_kernel<<<224, 256>>>(We1, We2, Wc1, Wn1, Wn2);

    cudaFuncSetAttribute(h1_kernel, cudaFuncAttributeMaxDynamicSharedMemorySize, HL_SMEM);
    cudaFuncSetAttribute(node_kernel, cudaFuncAttributeMaxDynamicSharedMemorySize, HL_SMEM);
    cudaFuncSetAttribute(edge_kernel, cudaFuncAttributeMaxDynamicSharedMemorySize, EDGE_SMEM);

    h1_kernel<<<(NN + 127) / 128, 256, HL_SMEM>>>();

    edge_kernel<<<NE / 128, 256, EDGE_SMEM>>>(
        coord, eattr, ei, We1, be1, be2, bc1, Wc2, bc2,
        m_out, (float*)p_agg, (float*)p_cs4);

    node_kernel<<<(NN + 127) / 128, 256, HL_SMEM>>>(
        coord, bn1, bn2, (const float*)p_agg, (const float*)p_cs4, h_out, c_out);
}